// round 1
// baseline (speedup 1.0000x reference)
#include <cuda_runtime.h>
#include <math.h>
#include <float.h>

// ---------------- problem constants ----------------
#define NTOK   8192          // B*R*C tokens = 2*1024*4
#define EDIM   256
#define SPLIT  768
#define TOPK_  32
#define LATD   128
#define MLPD   1024

// ---------------- device scratch (no allocs allowed) ----------------
__device__ float g_QKV[NTOK*768];
__device__ float g_AO [NTOK*EDIM];
__device__ float g_X  [NTOK*EDIM];
__device__ float g_ST [NTOK*EDIM];
__device__ float g_IQ [NTOK*32];
__device__ float g_IK [NTOK*32];
__device__ float g_SC [3*32];          // [kind][bf][h], kind: 0=qs_tr 1=qs_te 2=ks
__device__ int   g_QI [NTOK*8];        // int8 packed, 32 per token
__device__ int   g_KI [NTOK*8];
__device__ int   g_IDX[NTOK*TOPK_];
__device__ float g_MQ [NTOK*EDIM];
__device__ float g_CD [NTOK*LATD];
__device__ float g_KV [NTOK*2*EDIM];
__device__ float g_AO2[NTOK*EDIM];
__device__ float g_ST2[NTOK*EDIM];
__device__ float g_X2 [NTOK*EDIM];
__device__ float g_H1 [NTOK*MLPD];
__device__ float g_X3 [NTOK*EDIM];

// ---------------- generic tiled SGEMM: C = A @ W^T (+bias)(+res)(gelu) ----------------
// A: [M,K] row-major, W: [N,K] row-major, C: [M,N]
#define BM 64
#define BN 64
#define BKT 16

template<int EPI>   // 0: +bias, 1: +bias +res, 2: gelu(acc+bias)
__global__ void sgemm(const float* __restrict__ A, const float* __restrict__ W,
                      const float* __restrict__ bias, const float* __restrict__ res,
                      float* __restrict__ C, int M, int N, int K) {
    __shared__ float As[BKT][BM];
    __shared__ float Bs[BKT][BN];
    const int bm = blockIdx.y * BM;
    const int bn = blockIdx.x * BN;
    const int tid = threadIdx.x;
    const int tr = tid >> 4;          // 0..15
    const int tc = tid & 15;          // 0..15
    const int lr = tid >> 2;          // 0..63
    const int lc = (tid & 3) << 2;    // 0,4,8,12

    float acc[4][4] = {};

    for (int k0 = 0; k0 < K; k0 += BKT) {
        float4 a4 = make_float4(0.f,0.f,0.f,0.f);
        float4 b4 = make_float4(0.f,0.f,0.f,0.f);
        int am = bm + lr;
        if (am < M) a4 = *reinterpret_cast<const float4*>(&A[(size_t)am*K + k0 + lc]);
        int wn = bn + lr;
        if (wn < N) b4 = *reinterpret_cast<const float4*>(&W[(size_t)wn*K + k0 + lc]);
        As[lc+0][lr]=a4.x; As[lc+1][lr]=a4.y; As[lc+2][lr]=a4.z; As[lc+3][lr]=a4.w;
        Bs[lc+0][lr]=b4.x; Bs[lc+1][lr]=b4.y; Bs[lc+2][lr]=b4.z; Bs[lc+3][lr]=b4.w;
        __syncthreads();
        #pragma unroll
        for (int kk = 0; kk < BKT; kk++) {
            float4 av = *reinterpret_cast<const float4*>(&As[kk][tr<<2]);
            float4 bv = *reinterpret_cast<const float4*>(&Bs[kk][tc<<2]);
            float af[4] = {av.x, av.y, av.z, av.w};
            float bw[4] = {bv.x, bv.y, bv.z, bv.w};
            #pragma unroll
            for (int i = 0; i < 4; i++)
                #pragma unroll
                for (int j = 0; j < 4; j++)
                    acc[i][j] += af[i] * bw[j];
        }
        __syncthreads();
    }

    #pragma unroll
    for (int i = 0; i < 4; i++) {
        int m = bm + (tr<<2) + i;
        if (m >= M) continue;
        #pragma unroll
        for (int j = 0; j < 4; j++) {
            int n = bn + (tc<<2) + j;
            if (n >= N) continue;
            float v = acc[i][j];
            if (bias) v += bias[n];
            if (EPI == 1) v += res[(size_t)m*N + n];
            if (EPI == 2) v = 0.5f * v * (1.0f + erff(v * 0.7071067811865475f));
            C[(size_t)m*N + n] = v;
        }
    }
}

// ---------------- feature attention over C=4 tokens ----------------
__global__ void feat_attn(const float* __restrict__ QKV, float* __restrict__ AO) {
    int s = blockIdx.x;                   // sequence 0..2047
    int h = threadIdx.x >> 5;             // head (8 warps)
    int lane = threadIdx.x & 31;          // dh dim
    float q[4], k[4], v[4];
    #pragma unroll
    for (int c = 0; c < 4; c++) {
        const float* row = QKV + (size_t)(s*4 + c) * 768;
        q[c] = row[h*32 + lane];
        k[c] = row[256 + h*32 + lane];
        v[c] = row[512 + h*32 + lane];
    }
    float sc[4][4];
    #pragma unroll
    for (int a = 0; a < 4; a++)
        #pragma unroll
        for (int b = 0; b < 4; b++) {
            float p = q[a] * k[b];
            #pragma unroll
            for (int o = 16; o > 0; o >>= 1) p += __shfl_xor_sync(0xffffffffu, p, o);
            sc[a][b] = p * 0.17677669529663687f;   // 1/sqrt(32)
        }
    #pragma unroll
    for (int a = 0; a < 4; a++) {
        float mx = fmaxf(fmaxf(sc[a][0], sc[a][1]), fmaxf(sc[a][2], sc[a][3]));
        float e0 = expf(sc[a][0]-mx), e1 = expf(sc[a][1]-mx);
        float e2 = expf(sc[a][2]-mx), e3 = expf(sc[a][3]-mx);
        float den = e0 + e1 + e2 + e3;
        float o = (e0*v[0] + e1*v[1] + e2*v[2] + e3*v[3]) / den;
        AO[(size_t)(s*4 + a)*256 + h*32 + lane] = o;
    }
}

// ---------------- layernorm with layout remap ----------------
__device__ __forceinline__ float blockSum256(float x) {
    __shared__ float sm[8];
    #pragma unroll
    for (int o = 16; o > 0; o >>= 1) x += __shfl_xor_sync(0xffffffffu, x, o);
    if ((threadIdx.x & 31) == 0) sm[threadIdx.x >> 5] = x;
    __syncthreads();
    float s = 0.f;
    #pragma unroll
    for (int i = 0; i < 8; i++) s += sm[i];
    __syncthreads();
    return s;
}

// mode 0: identity; 1: sf->st; 2: st->sf
__global__ void ln_kernel(const float* __restrict__ X, const float* __restrict__ g,
                          const float* __restrict__ b, float* __restrict__ Y, int mode) {
    int t = blockIdx.x, e = threadIdx.x;
    float x = X[(size_t)t*256 + e];
    float m = blockSum256(x) * (1.0f/256.0f);
    float d = x - m;
    float v = blockSum256(d*d) * (1.0f/256.0f);
    float y = d * rsqrtf(v + 1e-5f) * g[e] + b[e];
    int ot;
    if (mode == 0) ot = t;
    else if (mode == 1) { int bb = t >> 12, r = (t >> 2) & 1023, c = t & 3; ot = ((bb<<2)|c)*1024 + r; }
    else { int bf = t >> 10, r = t & 1023; int bb = bf >> 2, c = bf & 3; ot = bb*4096 + r*4 + c; }
    Y[(size_t)ot*256 + e] = y;
}

// ---------------- indexer: scales / quantize / score+topk ----------------
__global__ void idx_scales(const float* __restrict__ IQ, const float* __restrict__ IK,
                           float* __restrict__ SC) {
    int bf = blockIdx.x, h = blockIdx.y, kind = blockIdx.z;
    const float* src = (kind == 2) ? IK : IQ;
    int r0 = (kind == 1) ? SPLIT : 0;
    int r1 = (kind == 1) ? 1024 : SPLIT;
    int n = (r1 - r0) * 8;
    float m = 0.0f;
    for (int i = threadIdx.x; i < n; i += 256) {
        int r = r0 + (i >> 3), d = i & 7;
        m = fmaxf(m, fabsf(src[(size_t)(bf*1024 + r)*32 + h*8 + d]));
    }
    __shared__ float sm[8];
    #pragma unroll
    for (int o = 16; o > 0; o >>= 1) m = fmaxf(m, __shfl_xor_sync(0xffffffffu, m, o));
    if ((threadIdx.x & 31) == 0) sm[threadIdx.x >> 5] = m;
    __syncthreads();
    if (threadIdx.x == 0) {
        float mm = sm[0];
        for (int i = 1; i < 8; i++) mm = fmaxf(mm, sm[i]);
        SC[kind*32 + bf*4 + h] = (mm + 1e-6f) / 127.0f;
    }
}

__global__ void idx_quant(const float* __restrict__ IQ, const float* __restrict__ IK,
                          const float* __restrict__ SC, int* __restrict__ QI, int* __restrict__ KI) {
    int idx = blockIdx.x * 256 + threadIdx.x;
    if (idx >= NTOK*32) return;
    int t = idx >> 5, j = idx & 31, h = j >> 3;
    int bf = t >> 10, r = t & 1023;
    char* qb = (char*)QI;
    char* kb = (char*)KI;
    float qs = SC[(r < SPLIT ? 0 : 1)*32 + bf*4 + h];
    float qv = rintf(IQ[idx] / qs);            // round half-to-even, matches jnp.round
    qv = fminf(fmaxf(qv, -127.0f), 127.0f);
    qb[idx] = (char)(int)qv;
    if (r < SPLIT) {
        float ks = SC[64 + bf*4 + h];
        float kv = rintf(IK[idx] / ks);
        kv = fminf(fmaxf(kv, -127.0f), 127.0f);
        kb[idx] = (char)(int)kv;
    } else {
        kb[idx] = 0;
    }
}

__global__ void idx_topk(const int* __restrict__ QI, const int* __restrict__ KI,
                         const float* __restrict__ SC, const float* __restrict__ ow,
                         int* __restrict__ IDX) {
    int t = blockIdx.x;
    int bf = t >> 10, r = t & 1023;
    __shared__ float red[SPLIT];
    __shared__ int sq[8];
    __shared__ float ssc[4], sow[4];
    if (threadIdx.x < 8) sq[threadIdx.x] = QI[t*8 + threadIdx.x];
    if (threadIdx.x < 4) {
        int h = threadIdx.x;
        float qs = SC[(r < SPLIT ? 0 : 1)*32 + bf*4 + h];
        float ks = SC[64 + bf*4 + h];
        ssc[h] = qs * ks;
        sow[h] = ow[h];
    }
    __syncthreads();
    for (int k = threadIdx.x; k < SPLIT; k += 256) {
        const int* kw = KI + (size_t)(bf*1024 + k)*8;
        float acc = 0.f;
        #pragma unroll
        for (int h = 0; h < 4; h++) {
            int d = __dp4a(sq[2*h], kw[2*h], __dp4a(sq[2*h+1], kw[2*h+1], 0));
            acc += fmaxf((float)d * ssc[h], 0.0f) * sow[h];
        }
        red[k] = acc;
    }
    __syncthreads();
    __shared__ float wv[8];
    __shared__ int wi[8];
    for (int sel = 0; sel < TOPK_; sel++) {
        float bv = -FLT_MAX; int bi = 0x7fffffff;
        for (int k = threadIdx.x; k < SPLIT; k += 256) {
            float v = red[k];
            if (v > bv) { bv = v; bi = k; }     // ascending scan: ties keep lowest index
        }
        #pragma unroll
        for (int o = 16; o > 0; o >>= 1) {
            float ov = __shfl_xor_sync(0xffffffffu, bv, o);
            int   oi = __shfl_xor_sync(0xffffffffu, bi, o);
            if (ov > bv || (ov == bv && oi < bi)) { bv = ov; bi = oi; }
        }
        if ((threadIdx.x & 31) == 0) { wv[threadIdx.x >> 5] = bv; wi[threadIdx.x >> 5] = bi; }
        __syncthreads();
        if (threadIdx.x == 0) {
            float fv = wv[0]; int fi = wi[0];
            for (int i = 1; i < 8; i++)
                if (wv[i] > fv || (wv[i] == fv && wi[i] < fi)) { fv = wv[i]; fi = wi[i]; }
            IDX[t*TOPK_ + sel] = fi;
            red[fi] = -FLT_MAX;
        }
        __syncthreads();
    }
}

// ---------------- sparse MLA attention over top-32 keys ----------------
__global__ void mla_attn(const float* __restrict__ MQ, const float* __restrict__ KV,
                         const int* __restrict__ IDX, float* __restrict__ AO2) {
    int t = blockIdx.x;
    int bf = t >> 10;
    int h = threadIdx.x >> 5, lane = threadIdx.x & 31;
    __shared__ int sidx[32];
    if (threadIdx.x < 32) sidx[threadIdx.x] = IDX[t*TOPK_ + threadIdx.x];
    __syncthreads();
    float q = MQ[(size_t)t*256 + h*32 + lane];
    float myscore = 0.0f;
    for (int j = 0; j < 32; j++) {
        int kt = bf*1024 + sidx[j];
        float kk = KV[(size_t)kt*512 + h*32 + lane];
        float p = q * kk;
        #pragma unroll
        for (int o = 16; o > 0; o >>= 1) p += __shfl_xor_sync(0xffffffffu, p, o);
        if (lane == j) myscore = p * 0.17677669529663687f;
    }
    float mx = myscore;
    #pragma unroll
    for (int o = 16; o > 0; o >>= 1) mx = fmaxf(mx, __shfl_xor_sync(0xffffffffu, mx, o));
    float e = expf(myscore - mx);
    float s = e;
    #pragma unroll
    for (int o = 16; o > 0; o >>= 1) s += __shfl_xor_sync(0xffffffffu, s, o);
    float w = e / s;
    float acc = 0.0f;
    for (int j = 0; j < 32; j++) {
        float wj = __shfl_sync(0xffffffffu, w, j);
        int kt = bf*1024 + sidx[j];
        acc += wj * KV[(size_t)kt*512 + 256 + h*32 + lane];
    }
    AO2[(size_t)t*256 + h*32 + lane] = acc;
}

// ---------------- host launcher ----------------
static float* symF(const void* sym) { void* p = nullptr; cudaGetSymbolAddress(&p, sym); return (float*)p; }
static int*   symI(const void* sym) { void* p = nullptr; cudaGetSymbolAddress(&p, sym); return (int*)p; }

extern "C" void kernel_launch(void* const* d_in, const int* in_sizes, int n_in,
                              void* d_out, int out_size) {
    (void)in_sizes; (void)n_in; (void)out_size;
    const float* src      = (const float*)d_in[0];
    const float* fa_in_w  = (const float*)d_in[2];
    const float* fa_in_b  = (const float*)d_in[3];
    const float* fa_out_w = (const float*)d_in[4];
    const float* fa_out_b = (const float*)d_in[5];
    const float* n1g = (const float*)d_in[6];
    const float* n1b = (const float*)d_in[7];
    const float* iqw = (const float*)d_in[8];
    const float* ikw = (const float*)d_in[9];
    const float* iow = (const float*)d_in[10];
    const float* mqw = (const float*)d_in[11];
    const float* mdw = (const float*)d_in[12];
    const float* muw = (const float*)d_in[13];
    const float* mow = (const float*)d_in[14];
    const float* n2g = (const float*)d_in[15];
    const float* n2b = (const float*)d_in[16];
    const float* l1w = (const float*)d_in[17];
    const float* l1b = (const float*)d_in[18];
    const float* l2w = (const float*)d_in[19];
    const float* l2b = (const float*)d_in[20];
    const float* n3g = (const float*)d_in[21];
    const float* n3b = (const float*)d_in[22];

    float* QKV = symF(g_QKV); float* AO  = symF(g_AO);  float* X   = symF(g_X);
    float* ST  = symF(g_ST);  float* IQ  = symF(g_IQ);  float* IK  = symF(g_IK);
    float* SC  = symF(g_SC);  int*   QI  = symI(g_QI);  int*   KI  = symI(g_KI);
    int*   IDX = symI(g_IDX); float* MQ  = symF(g_MQ);  float* CD  = symF(g_CD);
    float* KV  = symF(g_KV);  float* AO2 = symF(g_AO2); float* ST2 = symF(g_ST2);
    float* X2  = symF(g_X2);  float* H1  = symF(g_H1);  float* X3  = symF(g_X3);

    dim3 blk(256);
    auto grd = [](int M, int N) { return dim3((unsigned)((N+BN-1)/BN), (unsigned)((M+BM-1)/BM)); };

    // Stage A: feature attention + LN1
    sgemm<0><<<grd(NTOK,768), blk>>>(src, fa_in_w, fa_in_b, nullptr, QKV, NTOK, 768, 256);
    feat_attn<<<2048, blk>>>(QKV, AO);
    sgemm<1><<<grd(NTOK,256), blk>>>(AO, fa_out_w, fa_out_b, src, X, NTOK, 256, 256);
    ln_kernel<<<NTOK, blk>>>(X, n1g, n1b, ST, 1);

    // Stage B: indexer
    sgemm<0><<<grd(NTOK,32), blk>>>(ST, iqw, nullptr, nullptr, IQ, NTOK, 32, 256);
    sgemm<0><<<grd(NTOK,32), blk>>>(ST, ikw, nullptr, nullptr, IK, NTOK, 32, 256);
    idx_scales<<<dim3(8,4,3), blk>>>(IQ, IK, SC);
    idx_quant<<<NTOK*32/256, blk>>>(IQ, IK, SC, QI, KI);
    idx_topk<<<NTOK, blk>>>(QI, KI, SC, iow, IDX);

    // Stage C: sparse MLA (kv up-projection hoisted before gather: linear ops commute)
    sgemm<0><<<grd(NTOK,256), blk>>>(ST, mqw, nullptr, nullptr, MQ, NTOK, 256, 256);
    sgemm<0><<<grd(NTOK,128), blk>>>(ST, mdw, nullptr, nullptr, CD, NTOK, 128, 256);
    sgemm<0><<<grd(NTOK,512), blk>>>(CD, muw, nullptr, nullptr, KV, NTOK, 512, 128);
    mla_attn<<<NTOK, blk>>>(MQ, KV, IDX, AO2);
    sgemm<1><<<grd(NTOK,256), blk>>>(AO2, mow, nullptr, ST, ST2, NTOK, 256, 256);

    // Stage D: LN2 + MLP + LN3
    ln_kernel<<<NTOK, blk>>>(ST2, n2g, n2b, X2, 2);
    sgemm<2><<<grd(NTOK,MLPD), blk>>>(X2, l1w, l1b, nullptr, H1, NTOK, MLPD, 256);
    sgemm<1><<<grd(NTOK,256), blk>>>(H1, l2w, l2b, X2, X3, NTOK, 256, MLPD);
    ln_kernel<<<NTOK, blk>>>(X3, n3g, n3b, (float*)d_out, 0);
}

// round 2
// speedup vs baseline: 1.1112x; 1.1112x over previous
#include <cuda_runtime.h>
#include <math.h>
#include <float.h>

// ---------------- problem constants ----------------
#define NTOK   8192          // B*R*C tokens = 2*1024*4
#define EDIM   256
#define SPLIT  768
#define TOPK_  32
#define LATD   128
#define MLPD   1024

// ---------------- device scratch (no allocs allowed) ----------------
__device__ float g_QKV[NTOK*768];
__device__ float g_AO [NTOK*EDIM];
__device__ float g_X  [NTOK*EDIM];
__device__ float g_ST [NTOK*EDIM];
__device__ float g_IQ [NTOK*32];
__device__ float g_IK [NTOK*32];
__device__ float g_SC [3*32];          // [kind][bf][h]
__device__ int   g_QI [NTOK*8];
__device__ int   g_KI [NTOK*8];
__device__ int   g_IDX[NTOK*TOPK_];
__device__ float g_MQ [NTOK*EDIM];
__device__ float g_CD [NTOK*LATD];
__device__ float g_KV [NTOK*2*EDIM];
__device__ float g_AO2[NTOK*EDIM];
__device__ float g_ST2[NTOK*EDIM];
__device__ float g_X2 [NTOK*EDIM];
__device__ float g_H1 [NTOK*MLPD];
__device__ float g_X3 [NTOK*EDIM];

// ---------------- packed f32x2 helpers (Blackwell-only FFMA2 path) ----------------
__device__ __forceinline__ void fma2(unsigned long long& d, unsigned long long a, unsigned long long b) {
    asm("fma.rn.f32x2 %0, %1, %2, %0;" : "+l"(d) : "l"(a), "l"(b));
}
__device__ __forceinline__ unsigned long long dup2(float x) {
    unsigned long long r;
    asm("mov.b64 %0, {%1, %1};" : "=l"(r) : "f"(x));
    return r;
}
__device__ __forceinline__ float2 unpk(unsigned long long v) {
    float2 r;
    asm("mov.b64 {%0, %1}, %2;" : "=f"(r.x), "=f"(r.y) : "l"(v));
    return r;
}

// ---------------- f32x2 tiled SGEMM: C = A @ W^T (+bias)(+res)(gelu) ----------------
// A: [M,K] row-major, W: [N,K] row-major, C: [M,N]
// Tile 128x64, 256 threads, 8x4 per thread, accumulators packed f32x2 (row pairs).
// M must be a multiple of 128; K a multiple of 16; N guarded.
#define BM 128
#define BN 64
#define BKT 16

template<int EPI>   // 0: +bias, 1: +bias +res, 2: gelu(acc+bias)
__global__ void __launch_bounds__(256, 3)
sgemm(const float* __restrict__ A, const float* __restrict__ W,
      const float* __restrict__ bias, const float* __restrict__ res,
      float* __restrict__ C, int M, int N, int K) {
    __shared__ __align__(16) float As[BKT][BM];
    __shared__ __align__(16) float Bs[BKT][BN];
    const int bm = blockIdx.y * BM;
    const int bn = blockIdx.x * BN;
    const int tid = threadIdx.x;
    const int tr = tid >> 4;          // 0..15 (8 rows each)
    const int tc = tid & 15;          // 0..15 (4 cols each)
    const int lr = tid >> 2;          // 0..63
    const int lc = (tid & 3) << 2;    // 0,4,8,12

    unsigned long long acc[4][4];
    #pragma unroll
    for (int p = 0; p < 4; p++)
        #pragma unroll
        for (int j = 0; j < 4; j++) acc[p][j] = 0ULL;

    const int wn = bn + lr;
    const float* Arow0 = A + (size_t)(bm + lr) * K + lc;
    const float* Arow1 = A + (size_t)(bm + 64 + lr) * K + lc;
    const float* Wrow  = W + (size_t)wn * K + lc;

    for (int k0 = 0; k0 < K; k0 += BKT) {
        float4 a0 = *reinterpret_cast<const float4*>(Arow0 + k0);
        float4 a1 = *reinterpret_cast<const float4*>(Arow1 + k0);
        float4 b4 = make_float4(0.f, 0.f, 0.f, 0.f);
        if (wn < N) b4 = *reinterpret_cast<const float4*>(Wrow + k0);
        As[lc+0][lr]     = a0.x; As[lc+1][lr]     = a0.y; As[lc+2][lr]     = a0.z; As[lc+3][lr]     = a0.w;
        As[lc+0][64+lr]  = a1.x; As[lc+1][64+lr]  = a1.y; As[lc+2][64+lr]  = a1.z; As[lc+3][64+lr]  = a1.w;
        Bs[lc+0][lr]     = b4.x; Bs[lc+1][lr]     = b4.y; Bs[lc+2][lr]     = b4.z; Bs[lc+3][lr]     = b4.w;
        __syncthreads();
        #pragma unroll
        for (int kk = 0; kk < BKT; kk++) {
            ulonglong2 av0 = *reinterpret_cast<const ulonglong2*>(&As[kk][tr<<3]);
            ulonglong2 av1 = *reinterpret_cast<const ulonglong2*>(&As[kk][(tr<<3) + 4]);
            unsigned long long a[4] = {av0.x, av0.y, av1.x, av1.y};
            float4 bv = *reinterpret_cast<const float4*>(&Bs[kk][tc<<2]);
            unsigned long long b[4] = {dup2(bv.x), dup2(bv.y), dup2(bv.z), dup2(bv.w)};
            #pragma unroll
            for (int p = 0; p < 4; p++)
                #pragma unroll
                for (int j = 0; j < 4; j++)
                    fma2(acc[p][j], a[p], b[j]);
        }
        __syncthreads();
    }

    #pragma unroll
    for (int p = 0; p < 4; p++) {
        int m0 = bm + (tr<<3) + (p<<1);
        #pragma unroll
        for (int j = 0; j < 4; j++) {
            int n = bn + (tc<<2) + j;
            if (n >= N) continue;
            float2 v2 = unpk(acc[p][j]);
            float bz = bias ? bias[n] : 0.0f;
            float v0 = v2.x + bz;
            float v1 = v2.y + bz;
            if (EPI == 1) { v0 += res[(size_t)m0*N + n]; v1 += res[(size_t)(m0+1)*N + n]; }
            if (EPI == 2) {
                v0 = 0.5f * v0 * (1.0f + erff(v0 * 0.7071067811865475f));
                v1 = 0.5f * v1 * (1.0f + erff(v1 * 0.7071067811865475f));
            }
            C[(size_t)m0*N + n]     = v0;
            C[(size_t)(m0+1)*N + n] = v1;
        }
    }
}

// ---------------- feature attention over C=4 tokens ----------------
__global__ void feat_attn(const float* __restrict__ QKV, float* __restrict__ AO) {
    int s = blockIdx.x;                   // sequence 0..2047
    int h = threadIdx.x >> 5;             // head (8 warps)
    int lane = threadIdx.x & 31;          // dh dim
    float q[4], k[4], v[4];
    #pragma unroll
    for (int c = 0; c < 4; c++) {
        const float* row = QKV + (size_t)(s*4 + c) * 768;
        q[c] = row[h*32 + lane];
        k[c] = row[256 + h*32 + lane];
        v[c] = row[512 + h*32 + lane];
    }
    float sc[4][4];
    #pragma unroll
    for (int a = 0; a < 4; a++)
        #pragma unroll
        for (int b = 0; b < 4; b++) {
            float p = q[a] * k[b];
            #pragma unroll
            for (int o = 16; o > 0; o >>= 1) p += __shfl_xor_sync(0xffffffffu, p, o);
            sc[a][b] = p * 0.17677669529663687f;   // 1/sqrt(32)
        }
    #pragma unroll
    for (int a = 0; a < 4; a++) {
        float mx = fmaxf(fmaxf(sc[a][0], sc[a][1]), fmaxf(sc[a][2], sc[a][3]));
        float e0 = expf(sc[a][0]-mx), e1 = expf(sc[a][1]-mx);
        float e2 = expf(sc[a][2]-mx), e3 = expf(sc[a][3]-mx);
        float den = e0 + e1 + e2 + e3;
        float o = (e0*v[0] + e1*v[1] + e2*v[2] + e3*v[3]) / den;
        AO[(size_t)(s*4 + a)*256 + h*32 + lane] = o;
    }
}

// ---------------- layernorm, warp-per-token, with layout remap ----------------
// mode 0: identity; 1: sf->st; 2: st->sf
__global__ void ln_kernel(const float* __restrict__ X, const float* __restrict__ g,
                          const float* __restrict__ b, float* __restrict__ Y, int mode) {
    int t = blockIdx.x * 8 + (threadIdx.x >> 5);
    int lane = threadIdx.x & 31;
    const float* xr = X + (size_t)t * 256 + lane * 8;
    float4 x0 = *reinterpret_cast<const float4*>(xr);
    float4 x1 = *reinterpret_cast<const float4*>(xr + 4);
    float s = x0.x + x0.y + x0.z + x0.w + x1.x + x1.y + x1.z + x1.w;
    #pragma unroll
    for (int o = 16; o > 0; o >>= 1) s += __shfl_xor_sync(0xffffffffu, s, o);
    float m = s * (1.0f / 256.0f);
    float d[8] = {x0.x-m, x0.y-m, x0.z-m, x0.w-m, x1.x-m, x1.y-m, x1.z-m, x1.w-m};
    float vs = 0.f;
    #pragma unroll
    for (int i = 0; i < 8; i++) vs += d[i]*d[i];
    #pragma unroll
    for (int o = 16; o > 0; o >>= 1) vs += __shfl_xor_sync(0xffffffffu, vs, o);
    float inv = rsqrtf(vs * (1.0f/256.0f) + 1e-5f);
    float4 g0 = *reinterpret_cast<const float4*>(g + lane*8);
    float4 g1 = *reinterpret_cast<const float4*>(g + lane*8 + 4);
    float4 b0 = *reinterpret_cast<const float4*>(b + lane*8);
    float4 b1 = *reinterpret_cast<const float4*>(b + lane*8 + 4);
    float4 y0, y1;
    y0.x = d[0]*inv*g0.x + b0.x; y0.y = d[1]*inv*g0.y + b0.y;
    y0.z = d[2]*inv*g0.z + b0.z; y0.w = d[3]*inv*g0.w + b0.w;
    y1.x = d[4]*inv*g1.x + b1.x; y1.y = d[5]*inv*g1.y + b1.y;
    y1.z = d[6]*inv*g1.z + b1.z; y1.w = d[7]*inv*g1.w + b1.w;
    int ot;
    if (mode == 0) ot = t;
    else if (mode == 1) { int bb = t >> 12, r = (t >> 2) & 1023, c = t & 3; ot = ((bb<<2)|c)*1024 + r; }
    else { int bf = t >> 10, r = t & 1023; int bb = bf >> 2, c = bf & 3; ot = bb*4096 + r*4 + c; }
    float* yr = Y + (size_t)ot * 256 + lane * 8;
    *reinterpret_cast<float4*>(yr)     = y0;
    *reinterpret_cast<float4*>(yr + 4) = y1;
}

// ---------------- indexer: scales / quantize / score+topk ----------------
__global__ void idx_scales(const float* __restrict__ IQ, const float* __restrict__ IK,
                           float* __restrict__ SC) {
    int bf = blockIdx.x, h = blockIdx.y, kind = blockIdx.z;
    const float* src = (kind == 2) ? IK : IQ;
    int r0 = (kind == 1) ? SPLIT : 0;
    int r1 = (kind == 1) ? 1024 : SPLIT;
    int n = (r1 - r0) * 8;
    float m = 0.0f;
    for (int i = threadIdx.x; i < n; i += 256) {
        int r = r0 + (i >> 3), d = i & 7;
        m = fmaxf(m, fabsf(src[(size_t)(bf*1024 + r)*32 + h*8 + d]));
    }
    __shared__ float sm[8];
    #pragma unroll
    for (int o = 16; o > 0; o >>= 1) m = fmaxf(m, __shfl_xor_sync(0xffffffffu, m, o));
    if ((threadIdx.x & 31) == 0) sm[threadIdx.x >> 5] = m;
    __syncthreads();
    if (threadIdx.x == 0) {
        float mm = sm[0];
        for (int i = 1; i < 8; i++) mm = fmaxf(mm, sm[i]);
        SC[kind*32 + bf*4 + h] = (mm + 1e-6f) / 127.0f;
    }
}

__global__ void idx_quant(const float* __restrict__ IQ, const float* __restrict__ IK,
                          const float* __restrict__ SC, int* __restrict__ QI, int* __restrict__ KI) {
    int idx = blockIdx.x * 256 + threadIdx.x;
    if (idx >= NTOK*32) return;
    int t = idx >> 5, j = idx & 31, h = j >> 3;
    int bf = t >> 10, r = t & 1023;
    char* qb = (char*)QI;
    char* kb = (char*)KI;
    float qs = SC[(r < SPLIT ? 0 : 1)*32 + bf*4 + h];
    float qv = rintf(IQ[idx] / qs);
    qv = fminf(fmaxf(qv, -127.0f), 127.0f);
    qb[idx] = (char)(int)qv;
    if (r < SPLIT) {
        float ks = SC[64 + bf*4 + h];
        float kv = rintf(IK[idx] / ks);
        kv = fminf(fmaxf(kv, -127.0f), 127.0f);
        kb[idx] = (char)(int)kv;
    } else {
        kb[idx] = 0;
    }
}

__global__ void idx_topk(const int* __restrict__ QI, const int* __restrict__ KI,
                         const float* __restrict__ SC, const float* __restrict__ ow,
                         int* __restrict__ IDX) {
    int t = blockIdx.x;
    int bf = t >> 10, r = t & 1023;
    __shared__ float red[SPLIT];
    __shared__ int sq[8];
    __shared__ float ssc[4], sow[4];
    if (threadIdx.x < 8) sq[threadIdx.x] = QI[t*8 + threadIdx.x];
    if (threadIdx.x < 4) {
        int h = threadIdx.x;
        float qs = SC[(r < SPLIT ? 0 : 1)*32 + bf*4 + h];
        float ks = SC[64 + bf*4 + h];
        ssc[h] = qs * ks;
        sow[h] = ow[h];
    }
    __syncthreads();
    for (int k = threadIdx.x; k < SPLIT; k += 256) {
        const int* kw = KI + (size_t)(bf*1024 + k)*8;
        float acc = 0.f;
        #pragma unroll
        for (int h = 0; h < 4; h++) {
            int d = __dp4a(sq[2*h], kw[2*h], __dp4a(sq[2*h+1], kw[2*h+1], 0));
            acc += fmaxf((float)d * ssc[h], 0.0f) * sow[h];
        }
        red[k] = acc;
    }
    __syncthreads();
    __shared__ float wv[8];
    __shared__ int wi[8];
    for (int sel = 0; sel < TOPK_; sel++) {
        float bv = -FLT_MAX; int bi = 0x7fffffff;
        for (int k = threadIdx.x; k < SPLIT; k += 256) {
            float v = red[k];
            if (v > bv) { bv = v; bi = k; }
        }
        #pragma unroll
        for (int o = 16; o > 0; o >>= 1) {
            float ov = __shfl_xor_sync(0xffffffffu, bv, o);
            int   oi = __shfl_xor_sync(0xffffffffu, bi, o);
            if (ov > bv || (ov == bv && oi < bi)) { bv = ov; bi = oi; }
        }
        if ((threadIdx.x & 31) == 0) { wv[threadIdx.x >> 5] = bv; wi[threadIdx.x >> 5] = bi; }
        __syncthreads();
        if (threadIdx.x == 0) {
            float fv = wv[0]; int fi = wi[0];
            for (int i = 1; i < 8; i++)
                if (wv[i] > fv || (wv[i] == fv && wi[i] < fi)) { fv = wv[i]; fi = wi[i]; }
            IDX[t*TOPK_ + sel] = fi;
            red[fi] = -FLT_MAX;
        }
        __syncthreads();
    }
}

// ---------------- sparse MLA attention over top-32 keys ----------------
__global__ void mla_attn(const float* __restrict__ MQ, const float* __restrict__ KV,
                         const int* __restrict__ IDX, float* __restrict__ AO2) {
    int t = blockIdx.x;
    int bf = t >> 10;
    int h = threadIdx.x >> 5, lane = threadIdx.x & 31;
    __shared__ int sidx[32];
    if (threadIdx.x < 32) sidx[threadIdx.x] = IDX[t*TOPK_ + threadIdx.x];
    __syncthreads();
    float q = MQ[(size_t)t*256 + h*32 + lane];
    float myscore = 0.0f;
    for (int j = 0; j < 32; j++) {
        int kt = bf*1024 + sidx[j];
        float kk = KV[(size_t)kt*512 + h*32 + lane];
        float p = q * kk;
        #pragma unroll
        for (int o = 16; o > 0; o >>= 1) p += __shfl_xor_sync(0xffffffffu, p, o);
        if (lane == j) myscore = p * 0.17677669529663687f;
    }
    float mx = myscore;
    #pragma unroll
    for (int o = 16; o > 0; o >>= 1) mx = fmaxf(mx, __shfl_xor_sync(0xffffffffu, mx, o));
    float e = expf(myscore - mx);
    float s = e;
    #pragma unroll
    for (int o = 16; o > 0; o >>= 1) s += __shfl_xor_sync(0xffffffffu, s, o);
    float w = e / s;
    float acc = 0.0f;
    for (int j = 0; j < 32; j++) {
        float wj = __shfl_sync(0xffffffffu, w, j);
        int kt = bf*1024 + sidx[j];
        acc += wj * KV[(size_t)kt*512 + 256 + h*32 + lane];
    }
    AO2[(size_t)t*256 + h*32 + lane] = acc;
}

// ---------------- host launcher ----------------
static float* symF(const void* sym) { void* p = nullptr; cudaGetSymbolAddress(&p, sym); return (float*)p; }
static int*   symI(const void* sym) { void* p = nullptr; cudaGetSymbolAddress(&p, sym); return (int*)p; }

extern "C" void kernel_launch(void* const* d_in, const int* in_sizes, int n_in,
                              void* d_out, int out_size) {
    (void)in_sizes; (void)n_in; (void)out_size;
    const float* src      = (const float*)d_in[0];
    const float* fa_in_w  = (const float*)d_in[2];
    const float* fa_in_b  = (const float*)d_in[3];
    const float* fa_out_w = (const float*)d_in[4];
    const float* fa_out_b = (const float*)d_in[5];
    const float* n1g = (const float*)d_in[6];
    const float* n1b = (const float*)d_in[7];
    const float* iqw = (const float*)d_in[8];
    const float* ikw = (const float*)d_in[9];
    const float* iow = (const float*)d_in[10];
    const float* mqw = (const float*)d_in[11];
    const float* mdw = (const float*)d_in[12];
    const float* muw = (const float*)d_in[13];
    const float* mow = (const float*)d_in[14];
    const float* n2g = (const float*)d_in[15];
    const float* n2b = (const float*)d_in[16];
    const float* l1w = (const float*)d_in[17];
    const float* l1b = (const float*)d_in[18];
    const float* l2w = (const float*)d_in[19];
    const float* l2b = (const float*)d_in[20];
    const float* n3g = (const float*)d_in[21];
    const float* n3b = (const float*)d_in[22];

    float* QKV = symF(g_QKV); float* AO  = symF(g_AO);  float* X   = symF(g_X);
    float* ST  = symF(g_ST);  float* IQ  = symF(g_IQ);  float* IK  = symF(g_IK);
    float* SC  = symF(g_SC);  int*   QI  = symI(g_QI);  int*   KI  = symI(g_KI);
    int*   IDX = symI(g_IDX); float* MQ  = symF(g_MQ);  float* CD  = symF(g_CD);
    float* KV  = symF(g_KV);  float* AO2 = symF(g_AO2); float* ST2 = symF(g_ST2);
    float* X2  = symF(g_X2);  float* H1  = symF(g_H1);  float* X3  = symF(g_X3);

    dim3 blk(256);
    auto grd = [](int M, int N) { return dim3((unsigned)((N+BN-1)/BN), (unsigned)((M+BM-1)/BM)); };

    // Stage A: feature attention + LN1
    sgemm<0><<<grd(NTOK,768), blk>>>(src, fa_in_w, fa_in_b, nullptr, QKV, NTOK, 768, 256);
    feat_attn<<<2048, blk>>>(QKV, AO);
    sgemm<1><<<grd(NTOK,256), blk>>>(AO, fa_out_w, fa_out_b, src, X, NTOK, 256, 256);
    ln_kernel<<<NTOK/8, blk>>>(X, n1g, n1b, ST, 1);

    // Stage B: indexer
    sgemm<0><<<grd(NTOK,32), blk>>>(ST, iqw, nullptr, nullptr, IQ, NTOK, 32, 256);
    sgemm<0><<<grd(NTOK,32), blk>>>(ST, ikw, nullptr, nullptr, IK, NTOK, 32, 256);
    idx_scales<<<dim3(8,4,3), blk>>>(IQ, IK, SC);
    idx_quant<<<NTOK*32/256, blk>>>(IQ, IK, SC, QI, KI);
    idx_topk<<<NTOK, blk>>>(QI, KI, SC, iow, IDX);

    // Stage C: sparse MLA (kv up-projection hoisted before gather)
    sgemm<0><<<grd(NTOK,256), blk>>>(ST, mqw, nullptr, nullptr, MQ, NTOK, 256, 256);
    sgemm<0><<<grd(NTOK,128), blk>>>(ST, mdw, nullptr, nullptr, CD, NTOK, 128, 256);
    sgemm<0><<<grd(NTOK,512), blk>>>(CD, muw, nullptr, nullptr, KV, NTOK, 512, 128);
    mla_attn<<<NTOK, blk>>>(MQ, KV, IDX, AO2);
    sgemm<1><<<grd(NTOK,256), blk>>>(AO2, mow, nullptr, ST, ST2, NTOK, 256, 256);

    // Stage D: LN2 + MLP + LN3
    ln_kernel<<<NTOK/8, blk>>>(ST2, n2g, n2b, X2, 2);
    sgemm<2><<<grd(NTOK,MLPD), blk>>>(X2, l1w, l1b, nullptr, H1, NTOK, MLPD, 256);
    sgemm<1><<<grd(NTOK,256), blk>>>(H1, l2w, l2b, X2, X3, NTOK, 256, MLPD);
    ln_kernel<<<NTOK/8, blk>>>(X3, n3g, n3b, (float*)d_out, 0);
}

// round 4
// speedup vs baseline: 1.4459x; 1.3013x over previous
#include <cuda_runtime.h>
#include <cuda_bf16.h>
#include <math.h>
#include <float.h>
#include <stdint.h>

// ---------------- problem constants ----------------
#define NTOK   8192          // B*R*C tokens = 2*1024*4
#define EDIM   256
#define SPLIT  768
#define TOPK_  32
#define LATD   128
#define MLPD   1024

// ---------------- device scratch (no allocs allowed) ----------------
__device__ float g_QKV[NTOK*768];
__device__ float g_AO [NTOK*EDIM];
__device__ float g_X  [NTOK*EDIM];
__device__ float g_ST [NTOK*EDIM];
__device__ float g_IQ [NTOK*32];
__device__ float g_IK [NTOK*32];
__device__ float g_SC [3*32];
__device__ int   g_QI [NTOK*8];
__device__ int   g_KI [NTOK*8];
__device__ int   g_IDX[NTOK*TOPK_];
__device__ float g_MQ [NTOK*EDIM];
__device__ float g_CD [NTOK*LATD];
__device__ float g_KV [NTOK*2*EDIM];
__device__ float g_AO2[NTOK*EDIM];
__device__ float g_ST2[NTOK*EDIM];
__device__ float g_X2 [NTOK*EDIM];
__device__ float g_H1 [NTOK*MLPD];
__device__ float g_X3 [NTOK*EDIM];
// bf16 split buffers
__device__ __nv_bfloat16 g_Ahi[NTOK*MLPD];
__device__ __nv_bfloat16 g_Alo[NTOK*MLPD];
__device__ __nv_bfloat16 g_Whi[1024*256];
__device__ __nv_bfloat16 g_Wlo[1024*256];

// ---------------- helpers ----------------
__device__ __forceinline__ uint32_t s2u(const void* p) {
    uint32_t a;
    asm("{ .reg .u64 t; cvta.to.shared.u64 t, %1; cvt.u32.u64 %0, t; }" : "=r"(a) : "l"(p));
    return a;
}
__device__ __forceinline__ void ldsm4(uint32_t* r, uint32_t addr) {
    asm volatile("ldmatrix.sync.aligned.m8n8.x4.shared.b16 {%0,%1,%2,%3}, [%4];"
                 : "=r"(r[0]), "=r"(r[1]), "=r"(r[2]), "=r"(r[3]) : "r"(addr));
}
__device__ __forceinline__ void mma16816(float* d, const uint32_t* a, const uint32_t* b) {
    asm volatile("mma.sync.aligned.m16n8k16.row.col.f32.bf16.bf16.f32 "
                 "{%0,%1,%2,%3}, {%4,%5,%6,%7}, {%8,%9}, {%0,%1,%2,%3};"
                 : "+f"(d[0]), "+f"(d[1]), "+f"(d[2]), "+f"(d[3])
                 : "r"(a[0]), "r"(a[1]), "r"(a[2]), "r"(a[3]), "r"(b[0]), "r"(b[1]));
}

// ---------------- split conversion fp32 -> bf16 hi/lo ----------------
__global__ void cvt_split(const float* __restrict__ x, __nv_bfloat16* __restrict__ hi,
                          __nv_bfloat16* __restrict__ lo, int n) {
    int i = (blockIdx.x * 256 + threadIdx.x) * 4;
    if (i >= n) return;
    float4 v = *reinterpret_cast<const float4*>(x + i);
    __nv_bfloat16 h0 = __float2bfloat16(v.x);
    __nv_bfloat16 h1 = __float2bfloat16(v.y);
    __nv_bfloat16 h2 = __float2bfloat16(v.z);
    __nv_bfloat16 h3 = __float2bfloat16(v.w);
    __nv_bfloat16 l0 = __float2bfloat16(v.x - __bfloat162float(h0));
    __nv_bfloat16 l1 = __float2bfloat16(v.y - __bfloat162float(h1));
    __nv_bfloat16 l2 = __float2bfloat16(v.z - __bfloat162float(h2));
    __nv_bfloat16 l3 = __float2bfloat16(v.w - __bfloat162float(h3));
    __nv_bfloat162 ph0; ph0.x = h0; ph0.y = h1;
    __nv_bfloat162 ph1; ph1.x = h2; ph1.y = h3;
    __nv_bfloat162 pl0; pl0.x = l0; pl0.y = l1;
    __nv_bfloat162 pl1; pl1.x = l2; pl1.y = l3;
    *reinterpret_cast<__nv_bfloat162*>(hi + i)     = ph0;
    *reinterpret_cast<__nv_bfloat162*>(hi + i + 2) = ph1;
    *reinterpret_cast<__nv_bfloat162*>(lo + i)     = pl0;
    *reinterpret_cast<__nv_bfloat162*>(lo + i + 2) = pl1;
}

// ---------------- HMMA split-bf16 GEMM: C = A @ W^T (+bias)(+res)(gelu) ----------------
// A:[M,K] W:[N,K] row-major bf16 (hi/lo). CTA 128x128, 256 thr, 8 warps (4m x 2n).
// Warp tile 32x64 = 2 m16 x 8 n8 mma tiles. BK=32. M,N multiples of 128; K mult of 32.
#define PADH 40   // halves per smem row (80B stride: conflict-free ldmatrix)

template<int EPI>   // 0: +bias(opt); 1: +bias(opt)+res; 2: gelu(acc+bias)
__global__ void __launch_bounds__(256, 2)
hgemm(const __nv_bfloat16* __restrict__ Ahi, const __nv_bfloat16* __restrict__ Alo,
      const __nv_bfloat16* __restrict__ Whi, const __nv_bfloat16* __restrict__ Wlo,
      const float* __restrict__ bias, const float* __restrict__ res,
      float* __restrict__ C, int M, int N, int K) {
    __shared__ __align__(16) __nv_bfloat16 sm[4*128*PADH];
    __nv_bfloat16* sAh = sm;
    __nv_bfloat16* sAl = sm + 128*PADH;
    __nv_bfloat16* sBh = sm + 2*128*PADH;
    __nv_bfloat16* sBl = sm + 3*128*PADH;

    const int tid  = threadIdx.x;
    const int warp = tid >> 5, lane = tid & 31;
    const int wm = warp & 3, wn = warp >> 1 >> 1;   // wm 0..3, wn 0..1
    const int bm = blockIdx.y * 128, bn = blockIdx.x * 128;

    const int lrow = tid >> 1;          // 0..127
    const int lseg = (tid & 1) << 4;    // 0 or 16 halves

    float acc[2][8][4];
    #pragma unroll
    for (int i = 0; i < 2; i++)
        #pragma unroll
        for (int j = 0; j < 8; j++)
            #pragma unroll
            for (int l = 0; l < 4; l++) acc[i][j][l] = 0.0f;

    const uint32_t sb = s2u(sm);
    // ldmatrix lane address components
    const int a_r = (lane & 7) + ((lane >> 3) & 1) * 8;
    const int a_c = ((lane >> 4) & 1) * 8;
    const int b_r = (lane & 7) + ((lane >> 4) & 1) * 8;
    const int b_c = ((lane >> 3) & 1) * 8;

    const __nv_bfloat16* gAh = Ahi + (size_t)(bm + lrow)*K + lseg;
    const __nv_bfloat16* gAl = Alo + (size_t)(bm + lrow)*K + lseg;
    const __nv_bfloat16* gBh = Whi + (size_t)(bn + lrow)*K + lseg;
    const __nv_bfloat16* gBl = Wlo + (size_t)(bn + lrow)*K + lseg;
    __nv_bfloat16* s0 = sAh + lrow*PADH + lseg;
    __nv_bfloat16* s1 = sAl + lrow*PADH + lseg;
    __nv_bfloat16* s2 = sBh + lrow*PADH + lseg;
    __nv_bfloat16* s3 = sBl + lrow*PADH + lseg;

    for (int k0 = 0; k0 < K; k0 += 32) {
        *reinterpret_cast<uint4*>(s0)     = *reinterpret_cast<const uint4*>(gAh + k0);
        *reinterpret_cast<uint4*>(s0 + 8) = *reinterpret_cast<const uint4*>(gAh + k0 + 8);
        *reinterpret_cast<uint4*>(s1)     = *reinterpret_cast<const uint4*>(gAl + k0);
        *reinterpret_cast<uint4*>(s1 + 8) = *reinterpret_cast<const uint4*>(gAl + k0 + 8);
        *reinterpret_cast<uint4*>(s2)     = *reinterpret_cast<const uint4*>(gBh + k0);
        *reinterpret_cast<uint4*>(s2 + 8) = *reinterpret_cast<const uint4*>(gBh + k0 + 8);
        *reinterpret_cast<uint4*>(s3)     = *reinterpret_cast<const uint4*>(gBl + k0);
        *reinterpret_cast<uint4*>(s3 + 8) = *reinterpret_cast<const uint4*>(gBl + k0 + 8);
        __syncthreads();

        #pragma unroll
        for (int ks = 0; ks < 2; ks++) {
            uint32_t ah[2][4], al[2][4];
            #pragma unroll
            for (int mi = 0; mi < 2; mi++) {
                uint32_t off = ((wm*32 + mi*16 + a_r)*PADH + ks*16 + a_c) * 2;
                ldsm4(ah[mi], sb + off);
                ldsm4(al[mi], sb + 128*PADH*2 + off);
            }
            uint32_t bh[8][2], bl[8][2];
            #pragma unroll
            for (int pi = 0; pi < 4; pi++) {
                uint32_t off = ((wn*64 + pi*16 + b_r)*PADH + ks*16 + b_c) * 2;
                uint32_t t[4];
                ldsm4(t, sb + 2*128*PADH*2 + off);
                bh[2*pi][0]=t[0]; bh[2*pi][1]=t[1]; bh[2*pi+1][0]=t[2]; bh[2*pi+1][1]=t[3];
                ldsm4(t, sb + 3*128*PADH*2 + off);
                bl[2*pi][0]=t[0]; bl[2*pi][1]=t[1]; bl[2*pi+1][0]=t[2]; bl[2*pi+1][1]=t[3];
            }
            #pragma unroll
            for (int ni = 0; ni < 8; ni++)
                #pragma unroll
                for (int mi = 0; mi < 2; mi++) {
                    mma16816(acc[mi][ni], ah[mi], bh[ni]);   // hi*hi
                    mma16816(acc[mi][ni], ah[mi], bl[ni]);   // hi*lo
                    mma16816(acc[mi][ni], al[mi], bh[ni]);   // lo*hi
                }
        }
        __syncthreads();
    }

    // epilogue: d0,d1 -> row g cols gc,gc+1 ; d2,d3 -> row g+8
    const int gr = lane >> 2, gc = (lane & 3) * 2;
    #pragma unroll
    for (int mi = 0; mi < 2; mi++) {
        #pragma unroll
        for (int ni = 0; ni < 8; ni++) {
            int r0 = bm + wm*32 + mi*16 + gr;
            int cc = bn + wn*64 + ni*8 + gc;
            float2 v0 = make_float2(acc[mi][ni][0], acc[mi][ni][1]);
            float2 v1 = make_float2(acc[mi][ni][2], acc[mi][ni][3]);
            if (bias) {
                float2 bz = *reinterpret_cast<const float2*>(bias + cc);
                v0.x += bz.x; v0.y += bz.y; v1.x += bz.x; v1.y += bz.y;
            }
            if (EPI == 1) {
                float2 r0v = *reinterpret_cast<const float2*>(res + (size_t)r0*N + cc);
                float2 r1v = *reinterpret_cast<const float2*>(res + (size_t)(r0+8)*N + cc);
                v0.x += r0v.x; v0.y += r0v.y; v1.x += r1v.x; v1.y += r1v.y;
            }
            if (EPI == 2) {
                v0.x = 0.5f*v0.x*(1.0f + erff(v0.x*0.7071067811865475f));
                v0.y = 0.5f*v0.y*(1.0f + erff(v0.y*0.7071067811865475f));
                v1.x = 0.5f*v1.x*(1.0f + erff(v1.x*0.7071067811865475f));
                v1.y = 0.5f*v1.y*(1.0f + erff(v1.y*0.7071067811865475f));
            }
            *reinterpret_cast<float2*>(C + (size_t)r0*N + cc)     = v0;
            *reinterpret_cast<float2*>(C + (size_t)(r0+8)*N + cc) = v1;
        }
    }
}

// ---------------- fp32 SGEMM (N=32 indexer projections) ----------------
#define BM 128
#define BN 64
#define BKT 16
__global__ void __launch_bounds__(256, 3)
sgemm32(const float* __restrict__ A, const float* __restrict__ W,
        float* __restrict__ C, int M, int N, int K) {
    __shared__ __align__(16) float As[BKT][BM];
    __shared__ __align__(16) float Bs[BKT][BN];
    const int bm = blockIdx.y * BM;
    const int bn = blockIdx.x * BN;
    const int tid = threadIdx.x;
    const int tr = tid >> 4;
    const int tc = tid & 15;
    const int lr = tid >> 2;
    const int lc = (tid & 3) << 2;
    float acc[8][4] = {};
    const int wn = bn + lr;
    const float* Arow0 = A + (size_t)(bm + lr) * K + lc;
    const float* Arow1 = A + (size_t)(bm + 64 + lr) * K + lc;
    const float* Wrow  = W + (size_t)wn * K + lc;
    for (int k0 = 0; k0 < K; k0 += BKT) {
        float4 a0 = *reinterpret_cast<const float4*>(Arow0 + k0);
        float4 a1 = *reinterpret_cast<const float4*>(Arow1 + k0);
        float4 b4 = make_float4(0.f,0.f,0.f,0.f);
        if (wn < N) b4 = *reinterpret_cast<const float4*>(Wrow + k0);
        As[lc+0][lr]=a0.x; As[lc+1][lr]=a0.y; As[lc+2][lr]=a0.z; As[lc+3][lr]=a0.w;
        As[lc+0][64+lr]=a1.x; As[lc+1][64+lr]=a1.y; As[lc+2][64+lr]=a1.z; As[lc+3][64+lr]=a1.w;
        Bs[lc+0][lr]=b4.x; Bs[lc+1][lr]=b4.y; Bs[lc+2][lr]=b4.z; Bs[lc+3][lr]=b4.w;
        __syncthreads();
        #pragma unroll
        for (int kk = 0; kk < BKT; kk++) {
            float4 av0 = *reinterpret_cast<const float4*>(&As[kk][tr<<3]);
            float4 av1 = *reinterpret_cast<const float4*>(&As[kk][(tr<<3)+4]);
            float4 bv  = *reinterpret_cast<const float4*>(&Bs[kk][tc<<2]);
            float af[8] = {av0.x,av0.y,av0.z,av0.w,av1.x,av1.y,av1.z,av1.w};
            float bw[4] = {bv.x,bv.y,bv.z,bv.w};
            #pragma unroll
            for (int i = 0; i < 8; i++)
                #pragma unroll
                for (int j = 0; j < 4; j++)
                    acc[i][j] += af[i]*bw[j];
        }
        __syncthreads();
    }
    #pragma unroll
    for (int i = 0; i < 8; i++) {
        int m = bm + (tr<<3) + i;
        #pragma unroll
        for (int j = 0; j < 4; j++) {
            int n = bn + (tc<<2) + j;
            if (n < N) C[(size_t)m*N + n] = acc[i][j];
        }
    }
}

// ---------------- feature attention over C=4 tokens ----------------
__global__ void feat_attn(const float* __restrict__ QKV, float* __restrict__ AO) {
    int s = blockIdx.x;
    int h = threadIdx.x >> 5;
    int lane = threadIdx.x & 31;
    float q[4], k[4], v[4];
    #pragma unroll
    for (int c = 0; c < 4; c++) {
        const float* row = QKV + (size_t)(s*4 + c) * 768;
        q[c] = row[h*32 + lane];
        k[c] = row[256 + h*32 + lane];
        v[c] = row[512 + h*32 + lane];
    }
    float sc[4][4];
    #pragma unroll
    for (int a = 0; a < 4; a++)
        #pragma unroll
        for (int b = 0; b < 4; b++) {
            float p = q[a] * k[b];
            #pragma unroll
            for (int o = 16; o > 0; o >>= 1) p += __shfl_xor_sync(0xffffffffu, p, o);
            sc[a][b] = p * 0.17677669529663687f;
        }
    #pragma unroll
    for (int a = 0; a < 4; a++) {
        float mx = fmaxf(fmaxf(sc[a][0], sc[a][1]), fmaxf(sc[a][2], sc[a][3]));
        float e0 = expf(sc[a][0]-mx), e1 = expf(sc[a][1]-mx);
        float e2 = expf(sc[a][2]-mx), e3 = expf(sc[a][3]-mx);
        float den = e0 + e1 + e2 + e3;
        float o = (e0*v[0] + e1*v[1] + e2*v[2] + e3*v[3]) / den;
        AO[(size_t)(s*4 + a)*256 + h*32 + lane] = o;
    }
}

// ---------------- layernorm, warp-per-token, layout remap ----------------
__global__ void ln_kernel(const float* __restrict__ X, const float* __restrict__ g,
                          const float* __restrict__ b, float* __restrict__ Y, int mode) {
    int t = blockIdx.x * 8 + (threadIdx.x >> 5);
    int lane = threadIdx.x & 31;
    const float* xr = X + (size_t)t * 256 + lane * 8;
    float4 x0 = *reinterpret_cast<const float4*>(xr);
    float4 x1 = *reinterpret_cast<const float4*>(xr + 4);
    float s = x0.x + x0.y + x0.z + x0.w + x1.x + x1.y + x1.z + x1.w;
    #pragma unroll
    for (int o = 16; o > 0; o >>= 1) s += __shfl_xor_sync(0xffffffffu, s, o);
    float m = s * (1.0f / 256.0f);
    float d[8] = {x0.x-m, x0.y-m, x0.z-m, x0.w-m, x1.x-m, x1.y-m, x1.z-m, x1.w-m};
    float vs = 0.f;
    #pragma unroll
    for (int i = 0; i < 8; i++) vs += d[i]*d[i];
    #pragma unroll
    for (int o = 16; o > 0; o >>= 1) vs += __shfl_xor_sync(0xffffffffu, vs, o);
    float inv = rsqrtf(vs * (1.0f/256.0f) + 1e-5f);
    float4 g0 = *reinterpret_cast<const float4*>(g + lane*8);
    float4 g1 = *reinterpret_cast<const float4*>(g + lane*8 + 4);
    float4 b0 = *reinterpret_cast<const float4*>(b + lane*8);
    float4 b1 = *reinterpret_cast<const float4*>(b + lane*8 + 4);
    float4 y0, y1;
    y0.x = d[0]*inv*g0.x + b0.x; y0.y = d[1]*inv*g0.y + b0.y;
    y0.z = d[2]*inv*g0.z + b0.z; y0.w = d[3]*inv*g0.w + b0.w;
    y1.x = d[4]*inv*g1.x + b1.x; y1.y = d[5]*inv*g1.y + b1.y;
    y1.z = d[6]*inv*g1.z + b1.z; y1.w = d[7]*inv*g1.w + b1.w;
    int ot;
    if (mode == 0) ot = t;
    else if (mode == 1) { int bb = t >> 12, r = (t >> 2) & 1023, c = t & 3; ot = ((bb<<2)|c)*1024 + r; }
    else { int bf = t >> 10, r = t & 1023; int bb = bf >> 2, c = bf & 3; ot = bb*4096 + r*4 + c; }
    float* yr = Y + (size_t)ot * 256 + lane * 8;
    *reinterpret_cast<float4*>(yr)     = y0;
    *reinterpret_cast<float4*>(yr + 4) = y1;
}

// ---------------- indexer: scales / quantize / score+topk ----------------
__global__ void idx_scales(const float* __restrict__ IQ, const float* __restrict__ IK,
                           float* __restrict__ SC) {
    int bf = blockIdx.x, h = blockIdx.y, kind = blockIdx.z;
    const float* src = (kind == 2) ? IK : IQ;
    int r0 = (kind == 1) ? SPLIT : 0;
    int r1 = (kind == 1) ? 1024 : SPLIT;
    int n = (r1 - r0) * 8;
    float m = 0.0f;
    for (int i = threadIdx.x; i < n; i += 256) {
        int r = r0 + (i >> 3), d = i & 7;
        m = fmaxf(m, fabsf(src[(size_t)(bf*1024 + r)*32 + h*8 + d]));
    }
    __shared__ float sm[8];
    #pragma unroll
    for (int o = 16; o > 0; o >>= 1) m = fmaxf(m, __shfl_xor_sync(0xffffffffu, m, o));
    if ((threadIdx.x & 31) == 0) sm[threadIdx.x >> 5] = m;
    __syncthreads();
    if (threadIdx.x == 0) {
        float mm = sm[0];
        for (int i = 1; i < 8; i++) mm = fmaxf(mm, sm[i]);
        SC[kind*32 + bf*4 + h] = (mm + 1e-6f) / 127.0f;
    }
}

__global__ void idx_quant(const float* __restrict__ IQ, const float* __restrict__ IK,
                          const float* __restrict__ SC, int* __restrict__ QI, int* __restrict__ KI) {
    int idx = blockIdx.x * 256 + threadIdx.x;
    if (idx >= NTOK*32) return;
    int t = idx >> 5, j = idx & 31, h = j >> 3;
    int bf = t >> 10, r = t & 1023;
    char* qb = (char*)QI;
    char* kb = (char*)KI;
    float qs = SC[(r < SPLIT ? 0 : 1)*32 + bf*4 + h];
    float qv = rintf(IQ[idx] / qs);
    qv = fminf(fmaxf(qv, -127.0f), 127.0f);
    qb[idx] = (char)(int)qv;
    if (r < SPLIT) {
        float ks = SC[64 + bf*4 + h];
        float kv = rintf(IK[idx] / ks);
        kv = fminf(fmaxf(kv, -127.0f), 127.0f);
        kb[idx] = (char)(int)kv;
    } else {
        kb[idx] = 0;
    }
}

__global__ void idx_topk(const int* __restrict__ QI, const int* __restrict__ KI,
                         const float* __restrict__ SC, const float* __restrict__ ow,
                         int* __restrict__ IDX) {
    int t = blockIdx.x;
    int bf = t >> 10, r = t & 1023;
    __shared__ float red[SPLIT];
    __shared__ int sq[8];
    __shared__ float ssc[4], sow[4];
    if (threadIdx.x < 8) sq[threadIdx.x] = QI[t*8 + threadIdx.x];
    if (threadIdx.x < 4) {
        int h = threadIdx.x;
        float qs = SC[(r < SPLIT ? 0 : 1)*32 + bf*4 + h];
        float ks = SC[64 + bf*4 + h];
        ssc[h] = qs * ks;
        sow[h] = ow[h];
    }
    __syncthreads();
    for (int k = threadIdx.x; k < SPLIT; k += 256) {
        const int* kw = KI + (size_t)(bf*1024 + k)*8;
        float acc = 0.f;
        #pragma unroll
        for (int h = 0; h < 4; h++) {
            int d = __dp4a(sq[2*h], kw[2*h], __dp4a(sq[2*h+1], kw[2*h+1], 0));
            acc += fmaxf((float)d * ssc[h], 0.0f) * sow[h];
        }
        red[k] = acc;
    }
    __syncthreads();
    __shared__ float wv[8];
    __shared__ int wi[8];
    for (int sel = 0; sel < TOPK_; sel++) {
        float bv = -FLT_MAX; int bi = 0x7fffffff;
        for (int k = threadIdx.x; k < SPLIT; k += 256) {
            float v = red[k];
            if (v > bv) { bv = v; bi = k; }
        }
        #pragma unroll
        for (int o = 16; o > 0; o >>= 1) {
            float ov = __shfl_xor_sync(0xffffffffu, bv, o);
            int   oi = __shfl_xor_sync(0xffffffffu, bi, o);
            if (ov > bv || (ov == bv && oi < bi)) { bv = ov; bi = oi; }
        }
        if ((threadIdx.x & 31) == 0) { wv[threadIdx.x >> 5] = bv; wi[threadIdx.x >> 5] = bi; }
        __syncthreads();
        if (threadIdx.x == 0) {
            float fv = wv[0]; int fi = wi[0];
            for (int i = 1; i < 8; i++)
                if (wv[i] > fv || (wv[i] == fv && wi[i] < fi)) { fv = wv[i]; fi = wi[i]; }
            IDX[t*TOPK_ + sel] = fi;
            red[fi] = -FLT_MAX;
        }
        __syncthreads();
    }
}

// ---------------- sparse MLA attention over top-32 keys ----------------
__global__ void mla_attn(const float* __restrict__ MQ, const float* __restrict__ KV,
                         const int* __restrict__ IDX, float* __restrict__ AO2) {
    int t = blockIdx.x;
    int bf = t >> 10;
    int h = threadIdx.x >> 5, lane = threadIdx.x & 31;
    __shared__ int sidx[32];
    if (threadIdx.x < 32) sidx[threadIdx.x] = IDX[t*TOPK_ + threadIdx.x];
    __syncthreads();
    float q = MQ[(size_t)t*256 + h*32 + lane];
    float myscore = 0.0f;
    for (int j = 0; j < 32; j++) {
        int kt = bf*1024 + sidx[j];
        float kk = KV[(size_t)kt*512 + h*32 + lane];
        float p = q * kk;
        #pragma unroll
        for (int o = 16; o > 0; o >>= 1) p += __shfl_xor_sync(0xffffffffu, p, o);
        if (lane == j) myscore = p * 0.17677669529663687f;
    }
    float mx = myscore;
    #pragma unroll
    for (int o = 16; o > 0; o >>= 1) mx = fmaxf(mx, __shfl_xor_sync(0xffffffffu, mx, o));
    float e = expf(myscore - mx);
    float s = e;
    #pragma unroll
    for (int o = 16; o > 0; o >>= 1) s += __shfl_xor_sync(0xffffffffu, s, o);
    float w = e / s;
    float acc = 0.0f;
    for (int j = 0; j < 32; j++) {
        float wj = __shfl_sync(0xffffffffu, w, j);
        int kt = bf*1024 + sidx[j];
        acc += wj * KV[(size_t)kt*512 + 256 + h*32 + lane];
    }
    AO2[(size_t)t*256 + h*32 + lane] = acc;
}

// ---------------- host launcher ----------------
static float* symF(const void* sym) { void* p = nullptr; cudaGetSymbolAddress(&p, sym); return (float*)p; }
static int*   symI(const void* sym) { void* p = nullptr; cudaGetSymbolAddress(&p, sym); return (int*)p; }
static __nv_bfloat16* symB(const void* sym) { void* p = nullptr; cudaGetSymbolAddress(&p, sym); return (__nv_bfloat16*)p; }

extern "C" void kernel_launch(void* const* d_in, const int* in_sizes, int n_in,
                              void* d_out, int out_size) {
    (void)in_sizes; (void)n_in; (void)out_size;
    const float* src      = (const float*)d_in[0];
    const float* fa_in_w  = (const float*)d_in[2];
    const float* fa_in_b  = (const float*)d_in[3];
    const float* fa_out_w = (const float*)d_in[4];
    const float* fa_out_b = (const float*)d_in[5];
    const float* n1g = (const float*)d_in[6];
    const float* n1b = (const float*)d_in[7];
    const float* iqw = (const float*)d_in[8];
    const float* ikw = (const float*)d_in[9];
    const float* iow = (const float*)d_in[10];
    const float* mqw = (const float*)d_in[11];
    const float* mdw = (const float*)d_in[12];
    const float* muw = (const float*)d_in[13];
    const float* mow = (const float*)d_in[14];
    const float* n2g = (const float*)d_in[15];
    const float* n2b = (const float*)d_in[16];
    const float* l1w = (const float*)d_in[17];
    const float* l1b = (const float*)d_in[18];
    const float* l2w = (const float*)d_in[19];
    const float* l2b = (const float*)d_in[20];
    const float* n3g = (const float*)d_in[21];
    const float* n3b = (const float*)d_in[22];

    float* QKV = symF(g_QKV); float* AO  = symF(g_AO);  float* X   = symF(g_X);
    float* ST  = symF(g_ST);  float* IQ  = symF(g_IQ);  float* IK  = symF(g_IK);
    float* SC  = symF(g_SC);  int*   QI  = symI(g_QI);  int*   KI  = symI(g_KI);
    int*   IDX = symI(g_IDX); float* MQ  = symF(g_MQ);  float* CD  = symF(g_CD);
    float* KV  = symF(g_KV);  float* AO2 = symF(g_AO2); float* ST2 = symF(g_ST2);
    float* X2  = symF(g_X2);  float* H1  = symF(g_H1);  float* X3  = symF(g_X3);
    __nv_bfloat16* Ahi = symB(g_Ahi); __nv_bfloat16* Alo = symB(g_Alo);
    __nv_bfloat16* Whi = symB(g_Whi); __nv_bfloat16* Wlo = symB(g_Wlo);

    dim3 blk(256);
    auto cvtA = [&](const float* x, int n) { cvt_split<<<n/1024, blk>>>(x, Ahi, Alo, n); };
    auto cvtW = [&](const float* x, int n) { cvt_split<<<n/1024, blk>>>(x, Whi, Wlo, n); };
    auto g2 = [](int N) { return dim3((unsigned)(N/128), NTOK/128); };

    // Stage A: feature attention + LN1
    cvtA(src, NTOK*256);
    cvtW(fa_in_w, 768*256);
    hgemm<0><<<g2(768), blk>>>(Ahi, Alo, Whi, Wlo, fa_in_b, nullptr, QKV, NTOK, 768, 256);
    feat_attn<<<2048, blk>>>(QKV, AO);
    cvtA(AO, NTOK*256);
    cvtW(fa_out_w, 256*256);
    hgemm<1><<<g2(256), blk>>>(Ahi, Alo, Whi, Wlo, fa_out_b, src, X, NTOK, 256, 256);
    ln_kernel<<<NTOK/8, blk>>>(X, n1g, n1b, ST, 1);

    // Stage B: indexer (fp32 path, tiny)
    sgemm32<<<dim3(1, 64), blk>>>(ST, iqw, IQ, NTOK, 32, 256);
    sgemm32<<<dim3(1, 64), blk>>>(ST, ikw, IK, NTOK, 32, 256);
    idx_scales<<<dim3(8,4,3), blk>>>(IQ, IK, SC);
    idx_quant<<<NTOK*32/256, blk>>>(IQ, IK, SC, QI, KI);
    idx_topk<<<NTOK, blk>>>(QI, KI, SC, iow, IDX);

    // Stage C: sparse MLA (kv up-projection hoisted before gather)
    cvtA(ST, NTOK*256);
    cvtW(mqw, 256*256);
    hgemm<0><<<g2(256), blk>>>(Ahi, Alo, Whi, Wlo, nullptr, nullptr, MQ, NTOK, 256, 256);
    cvtW(mdw, 128*256);
    hgemm<0><<<g2(128), blk>>>(Ahi, Alo, Whi, Wlo, nullptr, nullptr, CD, NTOK, 128, 256);
    cvtA(CD, NTOK*128);
    cvtW(muw, 512*128);
    hgemm<0><<<g2(512), blk>>>(Ahi, Alo, Whi, Wlo, nullptr, nullptr, KV, NTOK, 512, 128);
    mla_attn<<<NTOK, blk>>>(MQ, KV, IDX, AO2);
    cvtA(AO2, NTOK*256);
    cvtW(mow, 256*256);
    hgemm<1><<<g2(256), blk>>>(Ahi, Alo, Whi, Wlo, nullptr, ST, ST2, NTOK, 256, 256);

    // Stage D: LN2 + MLP + LN3
    ln_kernel<<<NTOK/8, blk>>>(ST2, n2g, n2b, X2, 2);
    cvtA(X2, NTOK*256);
    cvtW(l1w, 1024*256);
    hgemm<2><<<g2(1024), blk>>>(Ahi, Alo, Whi, Wlo, l1b, nullptr, H1, NTOK, 1024, 256);
    cvtA(H1, NTOK*1024);
    cvtW(l2w, 256*1024);
    hgemm<1><<<g2(256), blk>>>(Ahi, Alo, Whi, Wlo, l2b, X2, X3, NTOK, 256, 1024);
    ln_kernel<<<NTOK/8, blk>>>(X3, n3g, n3b, (float*)d_out, 0);
}

// round 5
// speedup vs baseline: 1.5706x; 1.0862x over previous
#include <cuda_runtime.h>
#include <cuda_bf16.h>
#include <math.h>
#include <float.h>
#include <stdint.h>

// ---------------- problem constants ----------------
#define NTOK   8192          // B*R*C tokens = 2*1024*4
#define EDIM   256
#define SPLIT  768
#define TOPK_  32
#define LATD   128
#define MLPD   1024

typedef __nv_bfloat16 bf16;
typedef __nv_bfloat162 bf162;

// ---------------- device scratch (no allocs allowed) ----------------
__device__ float g_QKV[NTOK*768];
__device__ float g_X  [NTOK*EDIM];
__device__ float g_ST [NTOK*EDIM];
__device__ float g_IQ [NTOK*32];
__device__ float g_IK [NTOK*32];
__device__ float g_SC [3*32];
__device__ int   g_QI [NTOK*8];
__device__ int   g_KI [NTOK*8];
__device__ int   g_IDX[NTOK*TOPK_];
__device__ float g_MQ [NTOK*EDIM];
__device__ float g_KV [NTOK*2*EDIM];
__device__ float g_ST2[NTOK*EDIM];
__device__ float g_X2 [NTOK*EDIM];
__device__ float g_X3 [NTOK*EDIM];
// bf16 split buffers
__device__ bf16 g_SRCh[NTOK*EDIM],  g_SRCl[NTOK*EDIM];
__device__ bf16 g_AOh [NTOK*EDIM],  g_AOl [NTOK*EDIM];
__device__ bf16 g_STh [NTOK*EDIM],  g_STl [NTOK*EDIM];
__device__ bf16 g_CDh [NTOK*LATD],  g_CDl [NTOK*LATD];
__device__ bf16 g_AO2h[NTOK*EDIM],  g_AO2l[NTOK*EDIM];
__device__ bf16 g_X2h [NTOK*EDIM],  g_X2l [NTOK*EDIM];
__device__ bf16 g_H1h [NTOK*MLPD],  g_H1l [NTOK*MLPD];
__device__ bf16 g_Whi [1<<20],      g_Wlo [1<<20];

// weight offsets inside g_Whi/g_Wlo
#define W_FAIN  0
#define W_FAOUT 196608
#define W_MQ    262144
#define W_MD    327680
#define W_MU    360448
#define W_MO    425984
#define W_L1    491520
#define W_L2    753664

// ---------------- helpers ----------------
__device__ __forceinline__ uint32_t s2u(const void* p) {
    uint32_t a;
    asm("{ .reg .u64 t; cvta.to.shared.u64 t, %1; cvt.u32.u64 %0, t; }" : "=r"(a) : "l"(p));
    return a;
}
__device__ __forceinline__ void ldsm4(uint32_t* r, uint32_t addr) {
    asm volatile("ldmatrix.sync.aligned.m8n8.x4.shared.b16 {%0,%1,%2,%3}, [%4];"
                 : "=r"(r[0]), "=r"(r[1]), "=r"(r[2]), "=r"(r[3]) : "r"(addr));
}
__device__ __forceinline__ void mma16816(float* d, const uint32_t* a, const uint32_t* b) {
    asm volatile("mma.sync.aligned.m16n8k16.row.col.f32.bf16.bf16.f32 "
                 "{%0,%1,%2,%3}, {%4,%5,%6,%7}, {%8,%9}, {%0,%1,%2,%3};"
                 : "+f"(d[0]), "+f"(d[1]), "+f"(d[2]), "+f"(d[3])
                 : "r"(a[0]), "r"(a[1]), "r"(a[2]), "r"(a[3]), "r"(b[0]), "r"(b[1]));
}
#define CPA(dst, src) asm volatile("cp.async.cg.shared.global [%0], [%1], 16;" :: "r"(dst), "l"(src))
#define CPA_COMMIT()  asm volatile("cp.async.commit_group;" ::: "memory")
#define CPA_WAIT1()   asm volatile("cp.async.wait_group 1;" ::: "memory")
#define CPA_WAIT0()   asm volatile("cp.async.wait_group 0;" ::: "memory")

__device__ __forceinline__ bf162 split_hi(float a, float b, bf162& lo) {
    bf162 hi;
    hi.x = __float2bfloat16(a); hi.y = __float2bfloat16(b);
    lo.x = __float2bfloat16(a - __bfloat162float(hi.x));
    lo.y = __float2bfloat16(b - __bfloat162float(hi.y));
    return hi;
}

// ---------------- split conversion fp32 -> bf16 hi/lo ----------------
__global__ void cvt_split(const float* __restrict__ x, bf16* __restrict__ hi,
                          bf16* __restrict__ lo, int n) {
    int i = (blockIdx.x * 256 + threadIdx.x) * 4;
    if (i >= n) return;
    float4 v = *reinterpret_cast<const float4*>(x + i);
    bf162 l0, l1;
    bf162 h0 = split_hi(v.x, v.y, l0);
    bf162 h1 = split_hi(v.z, v.w, l1);
    *reinterpret_cast<bf162*>(hi + i)     = h0;
    *reinterpret_cast<bf162*>(hi + i + 2) = h1;
    *reinterpret_cast<bf162*>(lo + i)     = l0;
    *reinterpret_cast<bf162*>(lo + i + 2) = l1;
}

// ---------------- HMMA split-bf16 GEMM, cp.async 2-stage pipeline ----------------
// A:[M,K] W:[N,K] bf16 hi/lo. CTA 128xBN2, 256 thr, 8 warps (4m x 2n).
// BK=32. M mult of 128, N mult of BN2, K mult of 32.
#define PADH 40   // halves per smem row (80B stride)

template<int EPI, int BN2, int OSPLIT>   // EPI 0:+bias 1:+bias+res 2:gelu(acc+bias)
__global__ void __launch_bounds__(256)
hgemm(const bf16* __restrict__ Ahi, const bf16* __restrict__ Alo,
      const bf16* __restrict__ Whi, const bf16* __restrict__ Wlo,
      const float* __restrict__ bias, const float* __restrict__ res,
      float* __restrict__ C, bf16* __restrict__ Chi, bf16* __restrict__ Clo,
      int M, int N, int K) {
    constexpr int WNT  = BN2 / 2;        // warp n width
    constexpr int NPI  = WNT / 16;       // ldsm B tiles
    constexpr int NNI  = WNT / 8;        // mma n tiles
    constexpr int STAGE = 20480 + 2*BN2*80;

    extern __shared__ __align__(16) char smem[];
    const uint32_t sb = s2u(smem);
    const int tid  = threadIdx.x;
    const int warp = tid >> 5, lane = tid & 31;
    const int wm = warp & 3, wn = warp >> 2;
    const int bm = blockIdx.y * 128, bn = blockIdx.x * BN2;

    float acc[2][NNI][4];
    #pragma unroll
    for (int i = 0; i < 2; i++)
        #pragma unroll
        for (int j = 0; j < NNI; j++)
            #pragma unroll
            for (int l = 0; l < 4; l++) acc[i][j][l] = 0.0f;

    const int a_r = (lane & 7) + ((lane >> 3) & 1) * 8;
    const int a_c = ((lane >> 4) & 1) * 8;
    const int b_r = (lane & 7) + ((lane >> 4) & 1) * 8;
    const int b_c = ((lane >> 3) & 1) * 8;

    const int nch = K >> 5;

    auto load_stage = [&](int st, int k0) {
        uint32_t base = sb + st*STAGE;
        #pragma unroll
        for (int c = tid; c < 512; c += 256) {
            int row = c >> 2, seg = c & 3;
            uint32_t d = base + row*80 + seg*16;
            CPA(d,         Ahi + (size_t)(bm + row)*K + k0 + seg*8);
            CPA(d + 10240, Alo + (size_t)(bm + row)*K + k0 + seg*8);
        }
        #pragma unroll
        for (int c = tid; c < BN2*4; c += 256) {
            int row = c >> 2, seg = c & 3;
            uint32_t d = base + 20480 + row*80 + seg*16;
            CPA(d,           Whi + (size_t)(bn + row)*K + k0 + seg*8);
            CPA(d + BN2*80,  Wlo + (size_t)(bn + row)*K + k0 + seg*8);
        }
        CPA_COMMIT();
    };

    load_stage(0, 0);

    for (int c = 0; c < nch; c++) {
        if (c + 1 < nch) { load_stage((c+1) & 1, (c+1) << 5); CPA_WAIT1(); }
        else             { CPA_WAIT0(); }
        __syncthreads();

        const uint32_t base = sb + (c & 1)*STAGE;
        #pragma unroll
        for (int ks = 0; ks < 2; ks++) {
            uint32_t ah[2][4], al[2][4];
            #pragma unroll
            for (int mi = 0; mi < 2; mi++) {
                uint32_t off = base + ((wm*32 + mi*16 + a_r)*PADH + ks*16 + a_c) * 2;
                ldsm4(ah[mi], off);
                ldsm4(al[mi], off + 10240);
            }
            uint32_t bh[NNI][2], bl[NNI][2];
            #pragma unroll
            for (int pi = 0; pi < NPI; pi++) {
                uint32_t off = base + 20480 + ((wn*WNT + pi*16 + b_r)*PADH + ks*16 + b_c) * 2;
                uint32_t t[4];
                ldsm4(t, off);
                bh[2*pi][0]=t[0]; bh[2*pi][1]=t[1]; bh[2*pi+1][0]=t[2]; bh[2*pi+1][1]=t[3];
                ldsm4(t, off + BN2*80);
                bl[2*pi][0]=t[0]; bl[2*pi][1]=t[1]; bl[2*pi+1][0]=t[2]; bl[2*pi+1][1]=t[3];
            }
            #pragma unroll
            for (int ni = 0; ni < NNI; ni++)
                #pragma unroll
                for (int mi = 0; mi < 2; mi++) {
                    mma16816(acc[mi][ni], ah[mi], bh[ni]);   // hi*hi
                    mma16816(acc[mi][ni], ah[mi], bl[ni]);   // hi*lo
                    mma16816(acc[mi][ni], al[mi], bh[ni]);   // lo*hi
                }
        }
        __syncthreads();
    }

    // epilogue
    const int gr = lane >> 2, gc = (lane & 3) * 2;
    #pragma unroll
    for (int mi = 0; mi < 2; mi++) {
        #pragma unroll
        for (int ni = 0; ni < NNI; ni++) {
            int r0 = bm + wm*32 + mi*16 + gr;
            int cc = bn + wn*WNT + ni*8 + gc;
            float2 v0 = make_float2(acc[mi][ni][0], acc[mi][ni][1]);
            float2 v1 = make_float2(acc[mi][ni][2], acc[mi][ni][3]);
            if (bias) {
                float2 bz = *reinterpret_cast<const float2*>(bias + cc);
                v0.x += bz.x; v0.y += bz.y; v1.x += bz.x; v1.y += bz.y;
            }
            if (EPI == 1) {
                float2 r0v = *reinterpret_cast<const float2*>(res + (size_t)r0*N + cc);
                float2 r1v = *reinterpret_cast<const float2*>(res + (size_t)(r0+8)*N + cc);
                v0.x += r0v.x; v0.y += r0v.y; v1.x += r1v.x; v1.y += r1v.y;
            }
            if (EPI == 2) {
                v0.x = 0.5f*v0.x*(1.0f + erff(v0.x*0.7071067811865475f));
                v0.y = 0.5f*v0.y*(1.0f + erff(v0.y*0.7071067811865475f));
                v1.x = 0.5f*v1.x*(1.0f + erff(v1.x*0.7071067811865475f));
                v1.y = 0.5f*v1.y*(1.0f + erff(v1.y*0.7071067811865475f));
            }
            if (OSPLIT) {
                bf162 l0, l1;
                bf162 h0 = split_hi(v0.x, v0.y, l0);
                bf162 h1 = split_hi(v1.x, v1.y, l1);
                *reinterpret_cast<bf162*>(Chi + (size_t)r0*N + cc)     = h0;
                *reinterpret_cast<bf162*>(Clo + (size_t)r0*N + cc)     = l0;
                *reinterpret_cast<bf162*>(Chi + (size_t)(r0+8)*N + cc) = h1;
                *reinterpret_cast<bf162*>(Clo + (size_t)(r0+8)*N + cc) = l1;
            } else {
                *reinterpret_cast<float2*>(C + (size_t)r0*N + cc)     = v0;
                *reinterpret_cast<float2*>(C + (size_t)(r0+8)*N + cc) = v1;
            }
        }
    }
}

// ---------------- fp32 SGEMM (N=32 indexer projections) ----------------
#define BM 128
#define BN 64
#define BKT 16
__global__ void __launch_bounds__(256, 3)
sgemm32(const float* __restrict__ A, const float* __restrict__ W,
        float* __restrict__ C, int M, int N, int K) {
    __shared__ __align__(16) float As[BKT][BM];
    __shared__ __align__(16) float Bs[BKT][BN];
    const int bm = blockIdx.y * BM;
    const int bn = blockIdx.x * BN;
    const int tid = threadIdx.x;
    const int tr = tid >> 4;
    const int tc = tid & 15;
    const int lr = tid >> 2;
    const int lc = (tid & 3) << 2;
    float acc[8][4] = {};
    const int wn = bn + lr;
    const float* Arow0 = A + (size_t)(bm + lr) * K + lc;
    const float* Arow1 = A + (size_t)(bm + 64 + lr) * K + lc;
    const float* Wrow  = W + (size_t)wn * K + lc;
    for (int k0 = 0; k0 < K; k0 += BKT) {
        float4 a0 = *reinterpret_cast<const float4*>(Arow0 + k0);
        float4 a1 = *reinterpret_cast<const float4*>(Arow1 + k0);
        float4 b4 = make_float4(0.f,0.f,0.f,0.f);
        if (wn < N) b4 = *reinterpret_cast<const float4*>(Wrow + k0);
        As[lc+0][lr]=a0.x; As[lc+1][lr]=a0.y; As[lc+2][lr]=a0.z; As[lc+3][lr]=a0.w;
        As[lc+0][64+lr]=a1.x; As[lc+1][64+lr]=a1.y; As[lc+2][64+lr]=a1.z; As[lc+3][64+lr]=a1.w;
        Bs[lc+0][lr]=b4.x; Bs[lc+1][lr]=b4.y; Bs[lc+2][lr]=b4.z; Bs[lc+3][lr]=b4.w;
        __syncthreads();
        #pragma unroll
        for (int kk = 0; kk < BKT; kk++) {
            float4 av0 = *reinterpret_cast<const float4*>(&As[kk][tr<<3]);
            float4 av1 = *reinterpret_cast<const float4*>(&As[kk][(tr<<3)+4]);
            float4 bv  = *reinterpret_cast<const float4*>(&Bs[kk][tc<<2]);
            float af[8] = {av0.x,av0.y,av0.z,av0.w,av1.x,av1.y,av1.z,av1.w};
            float bw[4] = {bv.x,bv.y,bv.z,bv.w};
            #pragma unroll
            for (int i = 0; i < 8; i++)
                #pragma unroll
                for (int j = 0; j < 4; j++)
                    acc[i][j] += af[i]*bw[j];
        }
        __syncthreads();
    }
    #pragma unroll
    for (int i = 0; i < 8; i++) {
        int m = bm + (tr<<3) + i;
        #pragma unroll
        for (int j = 0; j < 4; j++) {
            int n = bn + (tc<<2) + j;
            if (n < N) C[(size_t)m*N + n] = acc[i][j];
        }
    }
}

// ---------------- feature attention over C=4 tokens (bf16 split output) ----------------
__global__ void feat_attn(const float* __restrict__ QKV,
                          bf16* __restrict__ AOh, bf16* __restrict__ AOl) {
    int s = blockIdx.x;
    int h = threadIdx.x >> 5;
    int lane = threadIdx.x & 31;
    float q[4], k[4], v[4];
    #pragma unroll
    for (int c = 0; c < 4; c++) {
        const float* row = QKV + (size_t)(s*4 + c) * 768;
        q[c] = row[h*32 + lane];
        k[c] = row[256 + h*32 + lane];
        v[c] = row[512 + h*32 + lane];
    }
    float sc[4][4];
    #pragma unroll
    for (int a = 0; a < 4; a++)
        #pragma unroll
        for (int b = 0; b < 4; b++) {
            float p = q[a] * k[b];
            #pragma unroll
            for (int o = 16; o > 0; o >>= 1) p += __shfl_xor_sync(0xffffffffu, p, o);
            sc[a][b] = p * 0.17677669529663687f;
        }
    #pragma unroll
    for (int a = 0; a < 4; a++) {
        float mx = fmaxf(fmaxf(sc[a][0], sc[a][1]), fmaxf(sc[a][2], sc[a][3]));
        float e0 = expf(sc[a][0]-mx), e1 = expf(sc[a][1]-mx);
        float e2 = expf(sc[a][2]-mx), e3 = expf(sc[a][3]-mx);
        float den = e0 + e1 + e2 + e3;
        float o = (e0*v[0] + e1*v[1] + e2*v[2] + e3*v[3]) / den;
        bf16 oh = __float2bfloat16(o);
        bf16 ol = __float2bfloat16(o - __bfloat162float(oh));
        size_t idx = (size_t)(s*4 + a)*256 + h*32 + lane;
        AOh[idx] = oh;
        AOl[idx] = ol;
    }
}

// ---------------- layernorm, warp-per-token, layout remap, optional split out ----------------
__global__ void ln_kernel(const float* __restrict__ X, const float* __restrict__ g,
                          const float* __restrict__ b, float* __restrict__ Y,
                          bf16* __restrict__ Yhi, bf16* __restrict__ Ylo, int mode) {
    int t = blockIdx.x * 8 + (threadIdx.x >> 5);
    int lane = threadIdx.x & 31;
    const float* xr = X + (size_t)t * 256 + lane * 8;
    float4 x0 = *reinterpret_cast<const float4*>(xr);
    float4 x1 = *reinterpret_cast<const float4*>(xr + 4);
    float s = x0.x + x0.y + x0.z + x0.w + x1.x + x1.y + x1.z + x1.w;
    #pragma unroll
    for (int o = 16; o > 0; o >>= 1) s += __shfl_xor_sync(0xffffffffu, s, o);
    float m = s * (1.0f / 256.0f);
    float d[8] = {x0.x-m, x0.y-m, x0.z-m, x0.w-m, x1.x-m, x1.y-m, x1.z-m, x1.w-m};
    float vs = 0.f;
    #pragma unroll
    for (int i = 0; i < 8; i++) vs += d[i]*d[i];
    #pragma unroll
    for (int o = 16; o > 0; o >>= 1) vs += __shfl_xor_sync(0xffffffffu, vs, o);
    float inv = rsqrtf(vs * (1.0f/256.0f) + 1e-5f);
    float y[8];
    const float* gp = g + lane*8;
    const float* bp = b + lane*8;
    #pragma unroll
    for (int i = 0; i < 8; i++) y[i] = d[i]*inv*gp[i] + bp[i];
    int ot;
    if (mode == 0) ot = t;
    else if (mode == 1) { int bb = t >> 12, r = (t >> 2) & 1023, c = t & 3; ot = ((bb<<2)|c)*1024 + r; }
    else { int bf = t >> 10, r = t & 1023; int bb = bf >> 2, c = bf & 3; ot = bb*4096 + r*4 + c; }
    float* yr = Y + (size_t)ot * 256 + lane * 8;
    float4 y0 = make_float4(y[0], y[1], y[2], y[3]);
    float4 y1 = make_float4(y[4], y[5], y[6], y[7]);
    *reinterpret_cast<float4*>(yr)     = y0;
    *reinterpret_cast<float4*>(yr + 4) = y1;
    if (Yhi) {
        size_t o2 = (size_t)ot * 256 + lane * 8;
        #pragma unroll
        for (int i = 0; i < 4; i++) {
            bf162 lo;
            bf162 hi = split_hi(y[2*i], y[2*i+1], lo);
            *reinterpret_cast<bf162*>(Yhi + o2 + 2*i) = hi;
            *reinterpret_cast<bf162*>(Ylo + o2 + 2*i) = lo;
        }
    }
}

// ---------------- indexer: scales / quantize / score+topk ----------------
__global__ void idx_scales(const float* __restrict__ IQ, const float* __restrict__ IK,
                           float* __restrict__ SC) {
    int bf = blockIdx.x, h = blockIdx.y, kind = blockIdx.z;
    const float* src = (kind == 2) ? IK : IQ;
    int r0 = (kind == 1) ? SPLIT : 0;
    int r1 = (kind == 1) ? 1024 : SPLIT;
    int n = (r1 - r0) * 8;
    float m = 0.0f;
    for (int i = threadIdx.x; i < n; i += 256) {
        int r = r0 + (i >> 3), d = i & 7;
        m = fmaxf(m, fabsf(src[(size_t)(bf*1024 + r)*32 + h*8 + d]));
    }
    __shared__ float sm[8];
    #pragma unroll
    for (int o = 16; o > 0; o >>= 1) m = fmaxf(m, __shfl_xor_sync(0xffffffffu, m, o));
    if ((threadIdx.x & 31) == 0) sm[threadIdx.x >> 5] = m;
    __syncthreads();
    if (threadIdx.x == 0) {
        float mm = sm[0];
        for (int i = 1; i < 8; i++) mm = fmaxf(mm, sm[i]);
        SC[kind*32 + bf*4 + h] = (mm + 1e-6f) / 127.0f;
    }
}

__global__ void idx_quant(const float* __restrict__ IQ, const float* __restrict__ IK,
                          const float* __restrict__ SC, int* __restrict__ QI, int* __restrict__ KI) {
    int idx = blockIdx.x * 256 + threadIdx.x;
    if (idx >= NTOK*32) return;
    int t = idx >> 5, j = idx & 31, h = j >> 3;
    int bf = t >> 10, r = t & 1023;
    char* qb = (char*)QI;
    char* kb = (char*)KI;
    float qs = SC[(r < SPLIT ? 0 : 1)*32 + bf*4 + h];
    float qv = rintf(IQ[idx] / qs);
    qv = fminf(fmaxf(qv, -127.0f), 127.0f);
    qb[idx] = (char)(int)qv;
    if (r < SPLIT) {
        float ks = SC[64 + bf*4 + h];
        float kv = rintf(IK[idx] / ks);
        kv = fminf(fmaxf(kv, -127.0f), 127.0f);
        kb[idx] = (char)(int)kv;
    } else {
        kb[idx] = 0;
    }
}

__global__ void idx_topk(const int* __restrict__ QI, const int* __restrict__ KI,
                         const float* __restrict__ SC, const float* __restrict__ ow,
                         int* __restrict__ IDX) {
    int t = blockIdx.x;
    int bf = t >> 10, r = t & 1023;
    __shared__ float red[SPLIT];
    __shared__ int sq[8];
    __shared__ float ssc[4], sow[4];
    if (threadIdx.x < 8) sq[threadIdx.x] = QI[t*8 + threadIdx.x];
    if (threadIdx.x < 4) {
        int h = threadIdx.x;
        float qs = SC[(r < SPLIT ? 0 : 1)*32 + bf*4 + h];
        float ks = SC[64 + bf*4 + h];
        ssc[h] = qs * ks;
        sow[h] = ow[h];
    }
    __syncthreads();
    for (int k = threadIdx.x; k < SPLIT; k += 256) {
        const int* kw = KI + (size_t)(bf*1024 + k)*8;
        float acc = 0.f;
        #pragma unroll
        for (int h = 0; h < 4; h++) {
            int d = __dp4a(sq[2*h], kw[2*h], __dp4a(sq[2*h+1], kw[2*h+1], 0));
            acc += fmaxf((float)d * ssc[h], 0.0f) * sow[h];
        }
        red[k] = acc;
    }
    __syncthreads();
    __shared__ float wv[8];
    __shared__ int wi[8];
    for (int sel = 0; sel < TOPK_; sel++) {
        float bv = -FLT_MAX; int bi = 0x7fffffff;
        for (int k = threadIdx.x; k < SPLIT; k += 256) {
            float v = red[k];
            if (v > bv) { bv = v; bi = k; }
        }
        #pragma unroll
        for (int o = 16; o > 0; o >>= 1) {
            float ov = __shfl_xor_sync(0xffffffffu, bv, o);
            int   oi = __shfl_xor_sync(0xffffffffu, bi, o);
            if (ov > bv || (ov == bv && oi < bi)) { bv = ov; bi = oi; }
        }
        if ((threadIdx.x & 31) == 0) { wv[threadIdx.x >> 5] = bv; wi[threadIdx.x >> 5] = bi; }
        __syncthreads();
        if (threadIdx.x == 0) {
            float fv = wv[0]; int fi = wi[0];
            for (int i = 1; i < 8; i++)
                if (wv[i] > fv || (wv[i] == fv && wi[i] < fi)) { fv = wv[i]; fi = wi[i]; }
            IDX[t*TOPK_ + sel] = fi;
            red[fi] = -FLT_MAX;
        }
        __syncthreads();
    }
}

// ---------------- sparse MLA attention over top-32 keys (bf16 split out) ----------------
__global__ void mla_attn(const float* __restrict__ MQ, const float* __restrict__ KV,
                         const int* __restrict__ IDX,
                         bf16* __restrict__ AO2h, bf16* __restrict__ AO2l) {
    int t = blockIdx.x;
    int bf = t >> 10;
    int h = threadIdx.x >> 5, lane = threadIdx.x & 31;
    __shared__ int sidx[32];
    if (threadIdx.x < 32) sidx[threadIdx.x] = IDX[t*TOPK_ + threadIdx.x];
    __syncthreads();
    float q = MQ[(size_t)t*256 + h*32 + lane];
    float myscore = 0.0f;
    for (int j = 0; j < 32; j++) {
        int kt = bf*1024 + sidx[j];
        float kk = KV[(size_t)kt*512 + h*32 + lane];
        float p = q * kk;
        #pragma unroll
        for (int o = 16; o > 0; o >>= 1) p += __shfl_xor_sync(0xffffffffu, p, o);
        if (lane == j) myscore = p * 0.17677669529663687f;
    }
    float mx = myscore;
    #pragma unroll
    for (int o = 16; o > 0; o >>= 1) mx = fmaxf(mx, __shfl_xor_sync(0xffffffffu, mx, o));
    float e = expf(myscore - mx);
    float s = e;
    #pragma unroll
    for (int o = 16; o > 0; o >>= 1) s += __shfl_xor_sync(0xffffffffu, s, o);
    float w = e / s;
    float acc = 0.0f;
    for (int j = 0; j < 32; j++) {
        float wj = __shfl_sync(0xffffffffu, w, j);
        int kt = bf*1024 + sidx[j];
        acc += wj * KV[(size_t)kt*512 + 256 + h*32 + lane];
    }
    bf16 oh = __float2bfloat16(acc);
    bf16 ol = __float2bfloat16(acc - __bfloat162float(oh));
    size_t idx = (size_t)t*256 + h*32 + lane;
    AO2h[idx] = oh;
    AO2l[idx] = ol;
}

// ---------------- host launcher ----------------
static float* symF(const void* sym) { void* p = nullptr; cudaGetSymbolAddress(&p, sym); return (float*)p; }
static int*   symI(const void* sym) { void* p = nullptr; cudaGetSymbolAddress(&p, sym); return (int*)p; }
static bf16*  symB(const void* sym) { void* p = nullptr; cudaGetSymbolAddress(&p, sym); return (bf16*)p; }

extern "C" void kernel_launch(void* const* d_in, const int* in_sizes, int n_in,
                              void* d_out, int out_size) {
    (void)in_sizes; (void)n_in; (void)out_size;
    const float* src      = (const float*)d_in[0];
    const float* fa_in_w  = (const float*)d_in[2];
    const float* fa_in_b  = (const float*)d_in[3];
    const float* fa_out_w = (const float*)d_in[4];
    const float* fa_out_b = (const float*)d_in[5];
    const float* n1g = (const float*)d_in[6];
    const float* n1b = (const float*)d_in[7];
    const float* iqw = (const float*)d_in[8];
    const float* ikw = (const float*)d_in[9];
    const float* iow = (const float*)d_in[10];
    const float* mqw = (const float*)d_in[11];
    const float* mdw = (const float*)d_in[12];
    const float* muw = (const float*)d_in[13];
    const float* mow = (const float*)d_in[14];
    const float* n2g = (const float*)d_in[15];
    const float* n2b = (const float*)d_in[16];
    const float* l1w = (const float*)d_in[17];
    const float* l1b = (const float*)d_in[18];
    const float* l2w = (const float*)d_in[19];
    const float* l2b = (const float*)d_in[20];
    const float* n3g = (const float*)d_in[21];
    const float* n3b = (const float*)d_in[22];

    float* QKV = symF(g_QKV); float* X   = symF(g_X);   float* ST  = symF(g_ST);
    float* IQ  = symF(g_IQ);  float* IK  = symF(g_IK);  float* SC  = symF(g_SC);
    int*   QI  = symI(g_QI);  int*   KI  = symI(g_KI);  int*   IDX = symI(g_IDX);
    float* MQ  = symF(g_MQ);  float* KV  = symF(g_KV);  float* ST2 = symF(g_ST2);
    float* X2  = symF(g_X2);  float* X3  = symF(g_X3);
    bf16 *SRCh=symB(g_SRCh), *SRCl=symB(g_SRCl);
    bf16 *AOh=symB(g_AOh),   *AOl=symB(g_AOl);
    bf16 *STh=symB(g_STh),   *STl=symB(g_STl);
    bf16 *CDh=symB(g_CDh),   *CDl=symB(g_CDl);
    bf16 *AO2h=symB(g_AO2h), *AO2l=symB(g_AO2l);
    bf16 *X2h=symB(g_X2h),   *X2l=symB(g_X2l);
    bf16 *H1h=symB(g_H1h),   *H1l=symB(g_H1l);
    bf16 *Wh=symB(g_Whi),    *Wl=symB(g_Wlo);

    static bool attrs_set = false;
    if (!attrs_set) {
        cudaFuncSetAttribute(hgemm<0,128,0>, cudaFuncAttributeMaxDynamicSharedMemorySize, 81920);
        cudaFuncSetAttribute(hgemm<1,128,0>, cudaFuncAttributeMaxDynamicSharedMemorySize, 81920);
        cudaFuncSetAttribute(hgemm<0,64,1>,  cudaFuncAttributeMaxDynamicSharedMemorySize, 61440);
        cudaFuncSetAttribute(hgemm<2,128,1>, cudaFuncAttributeMaxDynamicSharedMemorySize, 81920);
        attrs_set = true;
    }

    dim3 blk(256);
    // weight + src conversions (up front)
    cvt_split<<<2048, blk>>>(src, SRCh, SRCl, NTOK*256);
    cvt_split<<<192, blk>>>(fa_in_w,  Wh + W_FAIN,  Wl + W_FAIN,  196608);
    cvt_split<<<64,  blk>>>(fa_out_w, Wh + W_FAOUT, Wl + W_FAOUT, 65536);
    cvt_split<<<64,  blk>>>(mqw,      Wh + W_MQ,    Wl + W_MQ,    65536);
    cvt_split<<<32,  blk>>>(mdw,      Wh + W_MD,    Wl + W_MD,    32768);
    cvt_split<<<64,  blk>>>(muw,      Wh + W_MU,    Wl + W_MU,    65536);
    cvt_split<<<64,  blk>>>(mow,      Wh + W_MO,    Wl + W_MO,    65536);
    cvt_split<<<256, blk>>>(l1w,      Wh + W_L1,    Wl + W_L1,    262144);
    cvt_split<<<256, blk>>>(l2w,      Wh + W_L2,    Wl + W_L2,    262144);

    // Stage A: feature attention + LN1
    hgemm<0,128,0><<<dim3(6,64), blk, 81920>>>(SRCh, SRCl, Wh+W_FAIN, Wl+W_FAIN,
        fa_in_b, nullptr, QKV, nullptr, nullptr, NTOK, 768, 256);
    feat_attn<<<2048, blk>>>(QKV, AOh, AOl);
    hgemm<1,128,0><<<dim3(2,64), blk, 81920>>>(AOh, AOl, Wh+W_FAOUT, Wl+W_FAOUT,
        fa_out_b, src, X, nullptr, nullptr, NTOK, 256, 256);
    ln_kernel<<<NTOK/8, blk>>>(X, n1g, n1b, ST, STh, STl, 1);

    // Stage B: indexer (fp32 path)
    sgemm32<<<dim3(1, 64), blk>>>(ST, iqw, IQ, NTOK, 32, 256);
    sgemm32<<<dim3(1, 64), blk>>>(ST, ikw, IK, NTOK, 32, 256);
    idx_scales<<<dim3(8,4,3), blk>>>(IQ, IK, SC);
    idx_quant<<<NTOK*32/256, blk>>>(IQ, IK, SC, QI, KI);
    idx_topk<<<NTOK, blk>>>(QI, KI, SC, iow, IDX);

    // Stage C: sparse MLA (kv up-projection hoisted before gather)
    hgemm<0,128,0><<<dim3(2,64), blk, 81920>>>(STh, STl, Wh+W_MQ, Wl+W_MQ,
        nullptr, nullptr, MQ, nullptr, nullptr, NTOK, 256, 256);
    hgemm<0,64,1><<<dim3(2,64), blk, 61440>>>(STh, STl, Wh+W_MD, Wl+W_MD,
        nullptr, nullptr, nullptr, CDh, CDl, NTOK, 128, 256);
    hgemm<0,128,0><<<dim3(4,64), blk, 81920>>>(CDh, CDl, Wh+W_MU, Wl+W_MU,
        nullptr, nullptr, KV, nullptr, nullptr, NTOK, 512, 128);
    mla_attn<<<NTOK, blk>>>(MQ, KV, IDX, AO2h, AO2l);
    hgemm<1,128,0><<<dim3(2,64), blk, 81920>>>(AO2h, AO2l, Wh+W_MO, Wl+W_MO,
        nullptr, ST, ST2, nullptr, nullptr, NTOK, 256, 256);

    // Stage D: LN2 + MLP + LN3
    ln_kernel<<<NTOK/8, blk>>>(ST2, n2g, n2b, X2, X2h, X2l, 2);
    hgemm<2,128,1><<<dim3(8,64), blk, 81920>>>(X2h, X2l, Wh+W_L1, Wl+W_L1,
        l1b, nullptr, nullptr, H1h, H1l, NTOK, 1024, 256);
    hgemm<1,128,0><<<dim3(2,64), blk, 81920>>>(H1h, H1l, Wh+W_L2, Wl+W_L2,
        l2b, X2, X3, nullptr, nullptr, NTOK, 256, 1024);
    ln_kernel<<<NTOK/8, blk>>>(X3, n3g, n3b, (float*)d_out, nullptr, nullptr, 0);
}

// round 6
// speedup vs baseline: 1.8195x; 1.1585x over previous
#include <cuda_runtime.h>
#include <cuda_bf16.h>
#include <math.h>
#include <float.h>
#include <stdint.h>

// ---------------- problem constants ----------------
#define NTOK   8192          // B*R*C tokens = 2*1024*4
#define EDIM   256
#define SPLIT  768
#define TOPK_  32
#define LATD   128
#define MLPD   1024

typedef __nv_bfloat16 bf16;
typedef __nv_bfloat162 bf162;

// ---------------- device scratch (no allocs allowed) ----------------
__device__ float g_QKV[NTOK*768];
__device__ float g_X  [NTOK*EDIM];
__device__ float g_ST [NTOK*EDIM];
__device__ float g_IQK[NTOK*64];
__device__ float g_SC [3*32];
__device__ int   g_QI [NTOK*8];
__device__ int   g_KI [NTOK*8];
__device__ int   g_IDX[NTOK*TOPK_];
__device__ float g_MQ [NTOK*EDIM];
__device__ float g_KV [NTOK*2*EDIM];
__device__ float g_ST2[NTOK*EDIM];
__device__ float g_X2 [NTOK*EDIM];
__device__ float g_X3 [NTOK*EDIM];
// bf16 split buffers
__device__ bf16 g_SRCh[NTOK*EDIM],  g_SRCl[NTOK*EDIM];
__device__ bf16 g_AOh [NTOK*EDIM],  g_AOl [NTOK*EDIM];
__device__ bf16 g_STh [NTOK*EDIM],  g_STl [NTOK*EDIM];
__device__ bf16 g_CDh [NTOK*LATD],  g_CDl [NTOK*LATD];
__device__ bf16 g_AO2h[NTOK*EDIM],  g_AO2l[NTOK*EDIM];
__device__ bf16 g_X2h [NTOK*EDIM],  g_X2l [NTOK*EDIM];
__device__ bf16 g_H1h [NTOK*MLPD],  g_H1l [NTOK*MLPD];
__device__ bf16 g_Whi [1<<20],      g_Wlo [1<<20];

// weight offsets inside g_Whi/g_Wlo
#define W_FAIN  0
#define W_FAOUT 196608
#define W_MQ    262144
#define W_MD    327680
#define W_MU    360448
#define W_MO    425984
#define W_L1    491520
#define W_L2    753664
#define W_IDX   1015808

// ---------------- helpers ----------------
__device__ __forceinline__ uint32_t s2u(const void* p) {
    uint32_t a;
    asm("{ .reg .u64 t; cvta.to.shared.u64 t, %1; cvt.u32.u64 %0, t; }" : "=r"(a) : "l"(p));
    return a;
}
__device__ __forceinline__ void ldsm4(uint32_t* r, uint32_t addr) {
    asm volatile("ldmatrix.sync.aligned.m8n8.x4.shared.b16 {%0,%1,%2,%3}, [%4];"
                 : "=r"(r[0]), "=r"(r[1]), "=r"(r[2]), "=r"(r[3]) : "r"(addr));
}
__device__ __forceinline__ void mma16816(float* d, const uint32_t* a, const uint32_t* b) {
    asm volatile("mma.sync.aligned.m16n8k16.row.col.f32.bf16.bf16.f32 "
                 "{%0,%1,%2,%3}, {%4,%5,%6,%7}, {%8,%9}, {%0,%1,%2,%3};"
                 : "+f"(d[0]), "+f"(d[1]), "+f"(d[2]), "+f"(d[3])
                 : "r"(a[0]), "r"(a[1]), "r"(a[2]), "r"(a[3]), "r"(b[0]), "r"(b[1]));
}
#define CPA(dst, src) asm volatile("cp.async.cg.shared.global [%0], [%1], 16;" :: "r"(dst), "l"(src))
#define CPA_COMMIT()  asm volatile("cp.async.commit_group;" ::: "memory")
#define CPA_WAIT1()   asm volatile("cp.async.wait_group 1;" ::: "memory")
#define CPA_WAIT0()   asm volatile("cp.async.wait_group 0;" ::: "memory")

__device__ __forceinline__ bf162 split_hi(float a, float b, bf162& lo) {
    bf162 hi;
    hi.x = __float2bfloat16(a); hi.y = __float2bfloat16(b);
    lo.x = __float2bfloat16(a - __bfloat162float(hi.x));
    lo.y = __float2bfloat16(b - __bfloat162float(hi.y));
    return hi;
}
__device__ __forceinline__ void cvt4(const float* __restrict__ x, bf16* __restrict__ hi,
                                     bf16* __restrict__ lo, int i) {
    float4 v = *reinterpret_cast<const float4*>(x + i);
    bf162 l0, l1;
    bf162 h0 = split_hi(v.x, v.y, l0);
    bf162 h1 = split_hi(v.z, v.w, l1);
    *reinterpret_cast<bf162*>(hi + i)     = h0;
    *reinterpret_cast<bf162*>(hi + i + 2) = h1;
    *reinterpret_cast<bf162*>(lo + i)     = l0;
    *reinterpret_cast<bf162*>(lo + i + 2) = l1;
}

// ---------------- conversions ----------------
__global__ void cvt_split(const float* __restrict__ x, bf16* __restrict__ hi,
                          bf16* __restrict__ lo, int n) {
    int i = (blockIdx.x * 256 + threadIdx.x) * 4;
    if (i < n) cvt4(x, hi, lo, i);
}

// fa_in (192 blocks) + fa_out (64 blocks)
__global__ void wcvt_fa(const float* __restrict__ fin, const float* __restrict__ fout,
                        bf16* __restrict__ Wh, bf16* __restrict__ Wl) {
    int b = blockIdx.x;
    const float* src; int dst, rel;
    if (b < 192) { src = fin;  dst = W_FAIN;  rel = b; }
    else         { src = fout; dst = W_FAOUT; rel = b - 192; }
    int i = (rel*256 + threadIdx.x)*4;
    cvt4(src, Wh + dst, Wl + dst, i);
}

// remaining weights, one kernel (752 blocks)
__global__ void wcvt6(const float* __restrict__ mq, const float* __restrict__ md,
                      const float* __restrict__ mu, const float* __restrict__ mo,
                      const float* __restrict__ l1, const float* __restrict__ l2,
                      const float* __restrict__ iq, const float* __restrict__ ik,
                      bf16* __restrict__ Wh, bf16* __restrict__ Wl) {
    int b = blockIdx.x;
    const float* src; int dst, rel;
    if (b < 64)       { src = mq; dst = W_MQ;        rel = b; }
    else if (b < 96)  { src = md; dst = W_MD;        rel = b-64; }
    else if (b < 160) { src = mu; dst = W_MU;        rel = b-96; }
    else if (b < 224) { src = mo; dst = W_MO;        rel = b-160; }
    else if (b < 480) { src = l1; dst = W_L1;        rel = b-224; }
    else if (b < 736) { src = l2; dst = W_L2;        rel = b-480; }
    else if (b < 744) { src = iq; dst = W_IDX;       rel = b-736; }
    else              { src = ik; dst = W_IDX+8192;  rel = b-744; }
    int i = (rel*256 + threadIdx.x)*4;
    cvt4(src, Wh + dst, Wl + dst, i);
}

// ---------------- HMMA split-bf16 GEMM, cp.async 2-stage pipeline ----------------
#define PADH 40   // halves per smem row (80B stride)

template<int EPI, int BN2, int OSPLIT>   // EPI 0:+bias 1:+bias+res 2:gelu(acc+bias)
__global__ void __launch_bounds__(256)
hgemm(const bf16* __restrict__ Ahi, const bf16* __restrict__ Alo,
      const bf16* __restrict__ Whi, const bf16* __restrict__ Wlo,
      const float* __restrict__ bias, const float* __restrict__ res,
      float* __restrict__ C, bf16* __restrict__ Chi, bf16* __restrict__ Clo,
      int M, int N, int K) {
    constexpr int WNT  = BN2 / 2;
    constexpr int NPI  = WNT / 16;
    constexpr int NNI  = WNT / 8;
    constexpr int STAGE = 20480 + 2*BN2*80;

    extern __shared__ __align__(16) char smem[];
    const uint32_t sb = s2u(smem);
    const int tid  = threadIdx.x;
    const int warp = tid >> 5, lane = tid & 31;
    const int wm = warp & 3, wn = warp >> 2;
    const int bm = blockIdx.y * 128, bn = blockIdx.x * BN2;

    float acc[2][NNI][4];
    #pragma unroll
    for (int i = 0; i < 2; i++)
        #pragma unroll
        for (int j = 0; j < NNI; j++)
            #pragma unroll
            for (int l = 0; l < 4; l++) acc[i][j][l] = 0.0f;

    const int a_r = (lane & 7) + ((lane >> 3) & 1) * 8;
    const int a_c = ((lane >> 4) & 1) * 8;
    const int b_r = (lane & 7) + ((lane >> 4) & 1) * 8;
    const int b_c = ((lane >> 3) & 1) * 8;

    const int nch = K >> 5;

    auto load_stage = [&](int st, int k0) {
        uint32_t base = sb + st*STAGE;
        #pragma unroll
        for (int c = tid; c < 512; c += 256) {
            int row = c >> 2, seg = c & 3;
            uint32_t d = base + row*80 + seg*16;
            CPA(d,         Ahi + (size_t)(bm + row)*K + k0 + seg*8);
            CPA(d + 10240, Alo + (size_t)(bm + row)*K + k0 + seg*8);
        }
        #pragma unroll
        for (int c = tid; c < BN2*4; c += 256) {
            int row = c >> 2, seg = c & 3;
            uint32_t d = base + 20480 + row*80 + seg*16;
            CPA(d,           Whi + (size_t)(bn + row)*K + k0 + seg*8);
            CPA(d + BN2*80,  Wlo + (size_t)(bn + row)*K + k0 + seg*8);
        }
        CPA_COMMIT();
    };

    load_stage(0, 0);

    for (int c = 0; c < nch; c++) {
        if (c + 1 < nch) { load_stage((c+1) & 1, (c+1) << 5); CPA_WAIT1(); }
        else             { CPA_WAIT0(); }
        __syncthreads();

        const uint32_t base = sb + (c & 1)*STAGE;
        #pragma unroll
        for (int ks = 0; ks < 2; ks++) {
            uint32_t ah[2][4], al[2][4];
            #pragma unroll
            for (int mi = 0; mi < 2; mi++) {
                uint32_t off = base + ((wm*32 + mi*16 + a_r)*PADH + ks*16 + a_c) * 2;
                ldsm4(ah[mi], off);
                ldsm4(al[mi], off + 10240);
            }
            uint32_t bh[NNI][2], bl[NNI][2];
            #pragma unroll
            for (int pi = 0; pi < NPI; pi++) {
                uint32_t off = base + 20480 + ((wn*WNT + pi*16 + b_r)*PADH + ks*16 + b_c) * 2;
                uint32_t t[4];
                ldsm4(t, off);
                bh[2*pi][0]=t[0]; bh[2*pi][1]=t[1]; bh[2*pi+1][0]=t[2]; bh[2*pi+1][1]=t[3];
                ldsm4(t, off + BN2*80);
                bl[2*pi][0]=t[0]; bl[2*pi][1]=t[1]; bl[2*pi+1][0]=t[2]; bl[2*pi+1][1]=t[3];
            }
            #pragma unroll
            for (int ni = 0; ni < NNI; ni++)
                #pragma unroll
                for (int mi = 0; mi < 2; mi++) {
                    mma16816(acc[mi][ni], ah[mi], bh[ni]);
                    mma16816(acc[mi][ni], ah[mi], bl[ni]);
                    mma16816(acc[mi][ni], al[mi], bh[ni]);
                }
        }
        __syncthreads();
    }

    const int gr = lane >> 2, gc = (lane & 3) * 2;
    #pragma unroll
    for (int mi = 0; mi < 2; mi++) {
        #pragma unroll
        for (int ni = 0; ni < NNI; ni++) {
            int r0 = bm + wm*32 + mi*16 + gr;
            int cc = bn + wn*WNT + ni*8 + gc;
            float2 v0 = make_float2(acc[mi][ni][0], acc[mi][ni][1]);
            float2 v1 = make_float2(acc[mi][ni][2], acc[mi][ni][3]);
            if (bias) {
                float2 bz = *reinterpret_cast<const float2*>(bias + cc);
                v0.x += bz.x; v0.y += bz.y; v1.x += bz.x; v1.y += bz.y;
            }
            if (EPI == 1) {
                float2 r0v = *reinterpret_cast<const float2*>(res + (size_t)r0*N + cc);
                float2 r1v = *reinterpret_cast<const float2*>(res + (size_t)(r0+8)*N + cc);
                v0.x += r0v.x; v0.y += r0v.y; v1.x += r1v.x; v1.y += r1v.y;
            }
            if (EPI == 2) {
                v0.x = 0.5f*v0.x*(1.0f + erff(v0.x*0.7071067811865475f));
                v0.y = 0.5f*v0.y*(1.0f + erff(v0.y*0.7071067811865475f));
                v1.x = 0.5f*v1.x*(1.0f + erff(v1.x*0.7071067811865475f));
                v1.y = 0.5f*v1.y*(1.0f + erff(v1.y*0.7071067811865475f));
            }
            if (OSPLIT) {
                bf162 l0, l1;
                bf162 h0 = split_hi(v0.x, v0.y, l0);
                bf162 h1 = split_hi(v1.x, v1.y, l1);
                *reinterpret_cast<bf162*>(Chi + (size_t)r0*N + cc)     = h0;
                *reinterpret_cast<bf162*>(Clo + (size_t)r0*N + cc)     = l0;
                *reinterpret_cast<bf162*>(Chi + (size_t)(r0+8)*N + cc) = h1;
                *reinterpret_cast<bf162*>(Clo + (size_t)(r0+8)*N + cc) = l1;
            } else {
                *reinterpret_cast<float2*>(C + (size_t)r0*N + cc)     = v0;
                *reinterpret_cast<float2*>(C + (size_t)(r0+8)*N + cc) = v1;
            }
        }
    }
}

// ---------------- feature attention over C=4 tokens (bf16 split output) ----------------
__global__ void feat_attn(const float* __restrict__ QKV,
                          bf16* __restrict__ AOh, bf16* __restrict__ AOl) {
    int s = blockIdx.x;
    int h = threadIdx.x >> 5;
    int lane = threadIdx.x & 31;
    float q[4], k[4], v[4];
    #pragma unroll
    for (int c = 0; c < 4; c++) {
        const float* row = QKV + (size_t)(s*4 + c) * 768;
        q[c] = row[h*32 + lane];
        k[c] = row[256 + h*32 + lane];
        v[c] = row[512 + h*32 + lane];
    }
    float sc[4][4];
    #pragma unroll
    for (int a = 0; a < 4; a++)
        #pragma unroll
        for (int b = 0; b < 4; b++) {
            float p = q[a] * k[b];
            #pragma unroll
            for (int o = 16; o > 0; o >>= 1) p += __shfl_xor_sync(0xffffffffu, p, o);
            sc[a][b] = p * 0.17677669529663687f;
        }
    #pragma unroll
    for (int a = 0; a < 4; a++) {
        float mx = fmaxf(fmaxf(sc[a][0], sc[a][1]), fmaxf(sc[a][2], sc[a][3]));
        float e0 = expf(sc[a][0]-mx), e1 = expf(sc[a][1]-mx);
        float e2 = expf(sc[a][2]-mx), e3 = expf(sc[a][3]-mx);
        float den = e0 + e1 + e2 + e3;
        float o = (e0*v[0] + e1*v[1] + e2*v[2] + e3*v[3]) / den;
        bf16 oh = __float2bfloat16(o);
        bf16 ol = __float2bfloat16(o - __bfloat162float(oh));
        size_t idx = (size_t)(s*4 + a)*256 + h*32 + lane;
        AOh[idx] = oh;
        AOl[idx] = ol;
    }
}

// ---------------- layernorm, warp-per-token, layout remap, optional split out ----------------
__global__ void ln_kernel(const float* __restrict__ X, const float* __restrict__ g,
                          const float* __restrict__ b, float* __restrict__ Y,
                          bf16* __restrict__ Yhi, bf16* __restrict__ Ylo, int mode) {
    int t = blockIdx.x * 8 + (threadIdx.x >> 5);
    int lane = threadIdx.x & 31;
    const float* xr = X + (size_t)t * 256 + lane * 8;
    float4 x0 = *reinterpret_cast<const float4*>(xr);
    float4 x1 = *reinterpret_cast<const float4*>(xr + 4);
    float s = x0.x + x0.y + x0.z + x0.w + x1.x + x1.y + x1.z + x1.w;
    #pragma unroll
    for (int o = 16; o > 0; o >>= 1) s += __shfl_xor_sync(0xffffffffu, s, o);
    float m = s * (1.0f / 256.0f);
    float d[8] = {x0.x-m, x0.y-m, x0.z-m, x0.w-m, x1.x-m, x1.y-m, x1.z-m, x1.w-m};
    float vs = 0.f;
    #pragma unroll
    for (int i = 0; i < 8; i++) vs += d[i]*d[i];
    #pragma unroll
    for (int o = 16; o > 0; o >>= 1) vs += __shfl_xor_sync(0xffffffffu, vs, o);
    float inv = rsqrtf(vs * (1.0f/256.0f) + 1e-5f);
    float y[8];
    const float* gp = g + lane*8;
    const float* bp = b + lane*8;
    #pragma unroll
    for (int i = 0; i < 8; i++) y[i] = d[i]*inv*gp[i] + bp[i];
    int ot;
    if (mode == 0) ot = t;
    else if (mode == 1) { int bb = t >> 12, r = (t >> 2) & 1023, c = t & 3; ot = ((bb<<2)|c)*1024 + r; }
    else { int bf = t >> 10, r = t & 1023; int bb = bf >> 2, c = bf & 3; ot = bb*4096 + r*4 + c; }
    float* yr = Y + (size_t)ot * 256 + lane * 8;
    *reinterpret_cast<float4*>(yr)     = make_float4(y[0], y[1], y[2], y[3]);
    *reinterpret_cast<float4*>(yr + 4) = make_float4(y[4], y[5], y[6], y[7]);
    if (Yhi) {
        size_t o2 = (size_t)ot * 256 + lane * 8;
        #pragma unroll
        for (int i = 0; i < 4; i++) {
            bf162 lo;
            bf162 hi = split_hi(y[2*i], y[2*i+1], lo);
            *reinterpret_cast<bf162*>(Yhi + o2 + 2*i) = hi;
            *reinterpret_cast<bf162*>(Ylo + o2 + 2*i) = lo;
        }
    }
}

// ---------------- indexer: scales / quantize / score+topk ----------------
// IQK layout: [NTOK, 64]; cols 0..31 = q proj, cols 32..63 = k proj
__global__ void idx_scales(const float* __restrict__ IQK, float* __restrict__ SC) {
    int bf = blockIdx.x, h = blockIdx.y, kind = blockIdx.z;
    int r0 = (kind == 1) ? SPLIT : 0;
    int r1 = (kind == 1) ? 1024 : SPLIT;
    int cb = (kind == 2) ? 32 : 0;
    int n = (r1 - r0) * 8;
    float m = 0.0f;
    for (int i = threadIdx.x; i < n; i += 256) {
        int r = r0 + (i >> 3), d = i & 7;
        m = fmaxf(m, fabsf(IQK[(size_t)(bf*1024 + r)*64 + cb + h*8 + d]));
    }
    __shared__ float sm[8];
    #pragma unroll
    for (int o = 16; o > 0; o >>= 1) m = fmaxf(m, __shfl_xor_sync(0xffffffffu, m, o));
    if ((threadIdx.x & 31) == 0) sm[threadIdx.x >> 5] = m;
    __syncthreads();
    if (threadIdx.x == 0) {
        float mm = sm[0];
        for (int i = 1; i < 8; i++) mm = fmaxf(mm, sm[i]);
        SC[kind*32 + bf*4 + h] = (mm + 1e-6f) / 127.0f;
    }
}

__global__ void idx_quant(const float* __restrict__ IQK, const float* __restrict__ SC,
                          int* __restrict__ QI, int* __restrict__ KI) {
    int idx = blockIdx.x * 256 + threadIdx.x;
    if (idx >= NTOK*32) return;
    int t = idx >> 5, j = idx & 31, h = j >> 3;
    int bf = t >> 10, r = t & 1023;
    char* qb = (char*)QI;
    char* kb = (char*)KI;
    float qs = SC[(r < SPLIT ? 0 : 1)*32 + bf*4 + h];
    float qv = rintf(IQK[(size_t)t*64 + j] / qs);
    qv = fminf(fmaxf(qv, -127.0f), 127.0f);
    qb[idx] = (char)(int)qv;
    if (r < SPLIT) {
        float ks = SC[64 + bf*4 + h];
        float kv = rintf(IQK[(size_t)t*64 + 32 + j] / ks);
        kv = fminf(fmaxf(kv, -127.0f), 127.0f);
        kb[idx] = (char)(int)kv;
    } else {
        kb[idx] = 0;
    }
}

__global__ void idx_topk(const int* __restrict__ QI, const int* __restrict__ KI,
                         const float* __restrict__ SC, const float* __restrict__ ow,
                         int* __restrict__ IDX) {
    int t = blockIdx.x;
    int bf = t >> 10, r = t & 1023;
    __shared__ int sq[8];
    __shared__ float ssc[4], sow[4];
    __shared__ float swv[8];
    __shared__ int swi[8];
    __shared__ int winner;
    if (threadIdx.x < 8) sq[threadIdx.x] = QI[t*8 + threadIdx.x];
    if (threadIdx.x < 4) {
        int h = threadIdx.x;
        float qs = SC[(r < SPLIT ? 0 : 1)*32 + bf*4 + h];
        ssc[h] = qs * SC[64 + bf*4 + h];
        sow[h] = ow[h];
    }
    __syncthreads();
    // scores for 3 keys per thread, kept in registers
    float rv[3];
    #pragma unroll
    for (int i = 0; i < 3; i++) {
        int k = threadIdx.x + i*256;
        const int* kw = KI + (size_t)(bf*1024 + k)*8;
        float acc = 0.f;
        #pragma unroll
        for (int h = 0; h < 4; h++) {
            int d = __dp4a(sq[2*h], kw[2*h], __dp4a(sq[2*h+1], kw[2*h+1], 0));
            acc += fmaxf((float)d * ssc[h], 0.0f) * sow[h];
        }
        rv[i] = acc;
    }
    const int lane = threadIdx.x & 31;
    for (int sel = 0; sel < TOPK_; sel++) {
        float bv = rv[0]; int bi = threadIdx.x;
        if (rv[1] > bv) { bv = rv[1]; bi = threadIdx.x + 256; }
        if (rv[2] > bv) { bv = rv[2]; bi = threadIdx.x + 512; }
        #pragma unroll
        for (int o = 16; o > 0; o >>= 1) {
            float ov = __shfl_xor_sync(0xffffffffu, bv, o);
            int   oi = __shfl_xor_sync(0xffffffffu, bi, o);
            if (ov > bv || (ov == bv && oi < bi)) { bv = ov; bi = oi; }
        }
        if (lane == 0) { swv[threadIdx.x >> 5] = bv; swi[threadIdx.x >> 5] = bi; }
        __syncthreads();
        if (threadIdx.x == 0) {
            float fv = swv[0]; int fi = swi[0];
            #pragma unroll
            for (int i = 1; i < 8; i++)
                if (swv[i] > fv || (swv[i] == fv && swi[i] < fi)) { fv = swv[i]; fi = swi[i]; }
            IDX[t*TOPK_ + sel] = fi;
            winner = fi;
        }
        __syncthreads();
        int w = winner;
        if ((w & 255) == threadIdx.x) rv[w >> 8] = -FLT_MAX;
    }
}

// ---------------- sparse MLA attention over top-32 keys (bf16 split out) ----------------
__global__ void mla_attn(const float* __restrict__ MQ, const float* __restrict__ KV,
                         const int* __restrict__ IDX,
                         bf16* __restrict__ AO2h, bf16* __restrict__ AO2l) {
    int t = blockIdx.x;
    int bf = t >> 10;
    int h = threadIdx.x >> 5, lane = threadIdx.x & 31;
    __shared__ int sidx[32];
    if (threadIdx.x < 32) sidx[threadIdx.x] = IDX[t*TOPK_ + threadIdx.x];
    __syncthreads();
    float q = MQ[(size_t)t*256 + h*32 + lane];
    float myscore = 0.0f;
    for (int j = 0; j < 32; j++) {
        int kt = bf*1024 + sidx[j];
        float kk = KV[(size_t)kt*512 + h*32 + lane];
        float p = q * kk;
        #pragma unroll
        for (int o = 16; o > 0; o >>= 1) p += __shfl_xor_sync(0xffffffffu, p, o);
        if (lane == j) myscore = p * 0.17677669529663687f;
    }
    float mx = myscore;
    #pragma unroll
    for (int o = 16; o > 0; o >>= 1) mx = fmaxf(mx, __shfl_xor_sync(0xffffffffu, mx, o));
    float e = expf(myscore - mx);
    float s = e;
    #pragma unroll
    for (int o = 16; o > 0; o >>= 1) s += __shfl_xor_sync(0xffffffffu, s, o);
    float w = e / s;
    float acc = 0.0f;
    for (int j = 0; j < 32; j++) {
        float wj = __shfl_sync(0xffffffffu, w, j);
        int kt = bf*1024 + sidx[j];
        acc += wj * KV[(size_t)kt*512 + 256 + h*32 + lane];
    }
    bf16 oh = __float2bfloat16(acc);
    bf16 ol = __float2bfloat16(acc - __bfloat162float(oh));
    size_t idx = (size_t)t*256 + h*32 + lane;
    AO2h[idx] = oh;
    AO2l[idx] = ol;
}

// ---------------- host launcher ----------------
static float* symF(const void* sym) { void* p = nullptr; cudaGetSymbolAddress(&p, sym); return (float*)p; }
static int*   symI(const void* sym) { void* p = nullptr; cudaGetSymbolAddress(&p, sym); return (int*)p; }
static bf16*  symB(const void* sym) { void* p = nullptr; cudaGetSymbolAddress(&p, sym); return (bf16*)p; }

extern "C" void kernel_launch(void* const* d_in, const int* in_sizes, int n_in,
                              void* d_out, int out_size) {
    (void)in_sizes; (void)n_in; (void)out_size;
    const float* src      = (const float*)d_in[0];
    const float* fa_in_w  = (const float*)d_in[2];
    const float* fa_in_b  = (const float*)d_in[3];
    const float* fa_out_w = (const float*)d_in[4];
    const float* fa_out_b = (const float*)d_in[5];
    const float* n1g = (const float*)d_in[6];
    const float* n1b = (const float*)d_in[7];
    const float* iqw = (const float*)d_in[8];
    const float* ikw = (const float*)d_in[9];
    const float* iow = (const float*)d_in[10];
    const float* mqw = (const float*)d_in[11];
    const float* mdw = (const float*)d_in[12];
    const float* muw = (const float*)d_in[13];
    const float* mow = (const float*)d_in[14];
    const float* n2g = (const float*)d_in[15];
    const float* n2b = (const float*)d_in[16];
    const float* l1w = (const float*)d_in[17];
    const float* l1b = (const float*)d_in[18];
    const float* l2w = (const float*)d_in[19];
    const float* l2b = (const float*)d_in[20];
    const float* n3g = (const float*)d_in[21];
    const float* n3b = (const float*)d_in[22];

    float* QKV = symF(g_QKV); float* X   = symF(g_X);   float* ST  = symF(g_ST);
    float* IQK = symF(g_IQK); float* SC  = symF(g_SC);
    int*   QI  = symI(g_QI);  int*   KI  = symI(g_KI);  int*   IDX = symI(g_IDX);
    float* MQ  = symF(g_MQ);  float* KV  = symF(g_KV);  float* ST2 = symF(g_ST2);
    float* X2  = symF(g_X2);  float* X3  = symF(g_X3);
    bf16 *SRCh=symB(g_SRCh), *SRCl=symB(g_SRCl);
    bf16 *AOh=symB(g_AOh),   *AOl=symB(g_AOl);
    bf16 *STh=symB(g_STh),   *STl=symB(g_STl);
    bf16 *CDh=symB(g_CDh),   *CDl=symB(g_CDl);
    bf16 *AO2h=symB(g_AO2h), *AO2l=symB(g_AO2l);
    bf16 *X2h=symB(g_X2h),   *X2l=symB(g_X2l);
    bf16 *H1h=symB(g_H1h),   *H1l=symB(g_H1l);
    bf16 *Wh=symB(g_Whi),    *Wl=symB(g_Wlo);

    static cudaStream_t sW = nullptr, sB = nullptr;
    static cudaEvent_t evRoot = nullptr, evW = nullptr, ev1 = nullptr, evB = nullptr;
    if (!sW) {
        cudaStreamCreateWithFlags(&sW, cudaStreamNonBlocking);
        cudaStreamCreateWithFlags(&sB, cudaStreamNonBlocking);
        cudaEventCreateWithFlags(&evRoot, cudaEventDisableTiming);
        cudaEventCreateWithFlags(&evW,   cudaEventDisableTiming);
        cudaEventCreateWithFlags(&ev1,   cudaEventDisableTiming);
        cudaEventCreateWithFlags(&evB,   cudaEventDisableTiming);
        cudaFuncSetAttribute(hgemm<0,128,0>, cudaFuncAttributeMaxDynamicSharedMemorySize, 81920);
        cudaFuncSetAttribute(hgemm<1,128,0>, cudaFuncAttributeMaxDynamicSharedMemorySize, 81920);
        cudaFuncSetAttribute(hgemm<0,64,1>,  cudaFuncAttributeMaxDynamicSharedMemorySize, 61440);
        cudaFuncSetAttribute(hgemm<0,64,0>,  cudaFuncAttributeMaxDynamicSharedMemorySize, 61440);
        cudaFuncSetAttribute(hgemm<2,128,1>, cudaFuncAttributeMaxDynamicSharedMemorySize, 81920);
    }

    dim3 blk(256);

    // Fork: rest-of-weights conversion overlaps Stage A
    cudaEventRecord(evRoot, 0);
    cudaStreamWaitEvent(sW, evRoot, 0);
    wcvt6<<<752, blk, 0, sW>>>(mqw, mdw, muw, mow, l1w, l2w, iqw, ikw, Wh, Wl);
    cudaEventRecord(evW, sW);

    // Stage A (main stream)
    cvt_split<<<2048, blk>>>(src, SRCh, SRCl, NTOK*256);
    wcvt_fa<<<256, blk>>>(fa_in_w, fa_out_w, Wh, Wl);
    hgemm<0,128,0><<<dim3(6,64), blk, 81920>>>(SRCh, SRCl, Wh+W_FAIN, Wl+W_FAIN,
        fa_in_b, nullptr, QKV, nullptr, nullptr, NTOK, 768, 256);
    feat_attn<<<2048, blk>>>(QKV, AOh, AOl);
    hgemm<1,128,0><<<dim3(2,64), blk, 81920>>>(AOh, AOl, Wh+W_FAOUT, Wl+W_FAOUT,
        fa_out_b, src, X, nullptr, nullptr, NTOK, 256, 256);
    ln_kernel<<<NTOK/8, blk>>>(X, n1g, n1b, ST, STh, STl, 1);

    // Fork indexer branch (needs ST split + idx weights)
    cudaEventRecord(ev1, 0);
    cudaStreamWaitEvent(sB, ev1, 0);
    cudaStreamWaitEvent(sB, evW, 0);
    hgemm<0,64,0><<<dim3(1,64), blk, 61440, sB>>>(STh, STl, Wh+W_IDX, Wl+W_IDX,
        nullptr, nullptr, IQK, nullptr, nullptr, NTOK, 64, 256);
    idx_scales<<<dim3(8,4,3), blk, 0, sB>>>(IQK, SC);
    idx_quant<<<NTOK*32/256, blk, 0, sB>>>(IQK, SC, QI, KI);
    idx_topk<<<NTOK, blk, 0, sB>>>(QI, KI, SC, iow, IDX);
    cudaEventRecord(evB, sB);

    // Stage C GEMMs (main, concurrent with indexer branch)
    cudaStreamWaitEvent(0, evW, 0);
    hgemm<0,128,0><<<dim3(2,64), blk, 81920>>>(STh, STl, Wh+W_MQ, Wl+W_MQ,
        nullptr, nullptr, MQ, nullptr, nullptr, NTOK, 256, 256);
    hgemm<0,64,1><<<dim3(2,64), blk, 61440>>>(STh, STl, Wh+W_MD, Wl+W_MD,
        nullptr, nullptr, nullptr, CDh, CDl, NTOK, 128, 256);
    hgemm<0,128,0><<<dim3(4,64), blk, 81920>>>(CDh, CDl, Wh+W_MU, Wl+W_MU,
        nullptr, nullptr, KV, nullptr, nullptr, NTOK, 512, 128);

    // Join + attention
    cudaStreamWaitEvent(0, evB, 0);
    mla_attn<<<NTOK, blk>>>(MQ, KV, IDX, AO2h, AO2l);
    hgemm<1,128,0><<<dim3(2,64), blk, 81920>>>(AO2h, AO2l, Wh+W_MO, Wl+W_MO,
        nullptr, ST, ST2, nullptr, nullptr, NTOK, 256, 256);

    // Stage D
    ln_kernel<<<NTOK/8, blk>>>(ST2, n2g, n2b, X2, X2h, X2l, 2);
    hgemm<2,128,1><<<dim3(8,64), blk, 81920>>>(X2h, X2l, Wh+W_L1, Wl+W_L1,
        l1b, nullptr, nullptr, H1h, H1l, NTOK, 1024, 256);
    hgemm<1,128,0><<<dim3(2,64), blk, 81920>>>(H1h, H1l, Wh+W_L2, Wl+W_L2,
        l2b, X2, X3, nullptr, nullptr, NTOK, 256, 1024);
    ln_kernel<<<NTOK/8, blk>>>(X3, n3g, n3b, (float*)d_out, nullptr, nullptr, 0);
}

// round 7
// speedup vs baseline: 1.8470x; 1.0151x over previous
#include <cuda_runtime.h>
#include <cuda_bf16.h>
#include <math.h>
#include <float.h>
#include <stdint.h>

// ---------------- problem constants ----------------
#define NTOK   8192          // B*R*C tokens = 2*1024*4
#define EDIM   256
#define SPLIT  768
#define TOPK_  32
#define LATD   128
#define MLPD   1024

typedef __nv_bfloat16 bf16;
typedef __nv_bfloat162 bf162;

// ---------------- device scratch (no allocs allowed) ----------------
__device__ float g_QKV[NTOK*768];
__device__ float g_X  [NTOK*EDIM];
__device__ float g_ST [NTOK*EDIM];
__device__ float g_IQK[NTOK*64];
__device__ float g_SC [3*32];
__device__ int   g_QI [NTOK*8];
__device__ int   g_KI [NTOK*8];
__device__ int   g_IDX[NTOK*TOPK_];
__device__ float g_MQ [NTOK*EDIM];
__device__ float g_KV [NTOK*2*EDIM];
__device__ float g_ST2[NTOK*EDIM];
__device__ float g_X2 [NTOK*EDIM];
__device__ float g_X3 [NTOK*EDIM];
// bf16 split buffers
__device__ bf16 g_SRCh[NTOK*EDIM],  g_SRCl[NTOK*EDIM];
__device__ bf16 g_AOh [NTOK*EDIM],  g_AOl [NTOK*EDIM];
__device__ bf16 g_STh [NTOK*EDIM],  g_STl [NTOK*EDIM];
__device__ bf16 g_CDh [NTOK*LATD],  g_CDl [NTOK*LATD];
__device__ bf16 g_AO2h[NTOK*EDIM],  g_AO2l[NTOK*EDIM];
__device__ bf16 g_X2h [NTOK*EDIM],  g_X2l [NTOK*EDIM];
__device__ bf16 g_H1h [NTOK*MLPD],  g_H1l [NTOK*MLPD];
__device__ bf16 g_Whi [1<<20],      g_Wlo [1<<20];

// weight offsets inside g_Whi/g_Wlo  (W_MD directly follows W_MQ: merged GEMM)
#define W_FAIN  0
#define W_FAOUT 196608
#define W_MQ    262144
#define W_MD    327680
#define W_MU    360448
#define W_MO    425984
#define W_L1    491520
#define W_L2    753664
#define W_IDX   1015808

// ---------------- helpers ----------------
__device__ __forceinline__ uint32_t s2u(const void* p) {
    uint32_t a;
    asm("{ .reg .u64 t; cvta.to.shared.u64 t, %1; cvt.u32.u64 %0, t; }" : "=r"(a) : "l"(p));
    return a;
}
__device__ __forceinline__ void ldsm4(uint32_t* r, uint32_t addr) {
    asm volatile("ldmatrix.sync.aligned.m8n8.x4.shared.b16 {%0,%1,%2,%3}, [%4];"
                 : "=r"(r[0]), "=r"(r[1]), "=r"(r[2]), "=r"(r[3]) : "r"(addr));
}
__device__ __forceinline__ void mma16816(float* d, const uint32_t* a, const uint32_t* b) {
    asm volatile("mma.sync.aligned.m16n8k16.row.col.f32.bf16.bf16.f32 "
                 "{%0,%1,%2,%3}, {%4,%5,%6,%7}, {%8,%9}, {%0,%1,%2,%3};"
                 : "+f"(d[0]), "+f"(d[1]), "+f"(d[2]), "+f"(d[3])
                 : "r"(a[0]), "r"(a[1]), "r"(a[2]), "r"(a[3]), "r"(b[0]), "r"(b[1]));
}
#define CPA(dst, src) asm volatile("cp.async.cg.shared.global [%0], [%1], 16;" :: "r"(dst), "l"(src))
#define CPA_COMMIT()  asm volatile("cp.async.commit_group;" ::: "memory")
#define CPA_WAIT1()   asm volatile("cp.async.wait_group 1;" ::: "memory")
#define CPA_WAIT0()   asm volatile("cp.async.wait_group 0;" ::: "memory")

__device__ __forceinline__ bf162 split_hi(float a, float b, bf162& lo) {
    bf162 hi;
    hi.x = __float2bfloat16(a); hi.y = __float2bfloat16(b);
    lo.x = __float2bfloat16(a - __bfloat162float(hi.x));
    lo.y = __float2bfloat16(b - __bfloat162float(hi.y));
    return hi;
}
__device__ __forceinline__ void cvt4(const float* __restrict__ x, bf16* __restrict__ hi,
                                     bf16* __restrict__ lo, int i) {
    float4 v = *reinterpret_cast<const float4*>(x + i);
    bf162 l0, l1;
    bf162 h0 = split_hi(v.x, v.y, l0);
    bf162 h1 = split_hi(v.z, v.w, l1);
    *reinterpret_cast<bf162*>(hi + i)     = h0;
    *reinterpret_cast<bf162*>(hi + i + 2) = h1;
    *reinterpret_cast<bf162*>(lo + i)     = l0;
    *reinterpret_cast<bf162*>(lo + i + 2) = l1;
}

// ---------------- conversions ----------------
__global__ void cvt_split(const float* __restrict__ x, bf16* __restrict__ hi,
                          bf16* __restrict__ lo, int n) {
    int i = (blockIdx.x * 256 + threadIdx.x) * 4;
    if (i < n) cvt4(x, hi, lo, i);
}

__global__ void wcvt_fa(const float* __restrict__ fin, const float* __restrict__ fout,
                        bf16* __restrict__ Wh, bf16* __restrict__ Wl) {
    int b = blockIdx.x;
    const float* src; int dst, rel;
    if (b < 192) { src = fin;  dst = W_FAIN;  rel = b; }
    else         { src = fout; dst = W_FAOUT; rel = b - 192; }
    int i = (rel*256 + threadIdx.x)*4;
    cvt4(src, Wh + dst, Wl + dst, i);
}

__global__ void wcvt6(const float* __restrict__ mq, const float* __restrict__ md,
                      const float* __restrict__ mu, const float* __restrict__ mo,
                      const float* __restrict__ l1, const float* __restrict__ l2,
                      const float* __restrict__ iq, const float* __restrict__ ik,
                      bf16* __restrict__ Wh, bf16* __restrict__ Wl) {
    int b = blockIdx.x;
    const float* src; int dst, rel;
    if (b < 64)       { src = mq; dst = W_MQ;        rel = b; }
    else if (b < 96)  { src = md; dst = W_MD;        rel = b-64; }
    else if (b < 160) { src = mu; dst = W_MU;        rel = b-96; }
    else if (b < 224) { src = mo; dst = W_MO;        rel = b-160; }
    else if (b < 480) { src = l1; dst = W_L1;        rel = b-224; }
    else if (b < 736) { src = l2; dst = W_L2;        rel = b-480; }
    else if (b < 744) { src = iq; dst = W_IDX;       rel = b-736; }
    else              { src = ik; dst = W_IDX+8192;  rel = b-744; }
    int i = (rel*256 + threadIdx.x)*4;
    cvt4(src, Wh + dst, Wl + dst, i);
}

// ---------------- HMMA split-bf16 GEMM, cp.async 2-stage pipeline ----------------
// EPI: 0 +bias(opt); 1 +bias(opt)+res; 2 gelu(acc+bias); 3 mixed MQ(fp32,N256)/CD(split,N128)
#define PADH 40   // halves per smem row (80B stride)

template<int EPI, int BN2, int OSPLIT>
__global__ void __launch_bounds__(256, BN2 == 64 ? 3 : 2)
hgemm(const bf16* __restrict__ Ahi, const bf16* __restrict__ Alo,
      const bf16* __restrict__ Whi, const bf16* __restrict__ Wlo,
      const float* __restrict__ bias, const float* __restrict__ res,
      float* __restrict__ C, bf16* __restrict__ Chi, bf16* __restrict__ Clo,
      int M, int N, int K) {
    constexpr int WNT  = BN2 / 2;
    constexpr int NPI  = WNT / 16;
    constexpr int NNI  = WNT / 8;
    constexpr int STAGE = 20480 + 2*BN2*80;

    extern __shared__ __align__(16) char smem[];
    const uint32_t sb = s2u(smem);
    const int tid  = threadIdx.x;
    const int warp = tid >> 5, lane = tid & 31;
    const int wm = warp & 3, wn = warp >> 2;
    const int bm = blockIdx.y * 128, bn = blockIdx.x * BN2;

    float acc[2][NNI][4];
    #pragma unroll
    for (int i = 0; i < 2; i++)
        #pragma unroll
        for (int j = 0; j < NNI; j++)
            #pragma unroll
            for (int l = 0; l < 4; l++) acc[i][j][l] = 0.0f;

    const int a_r = (lane & 7) + ((lane >> 3) & 1) * 8;
    const int a_c = ((lane >> 4) & 1) * 8;
    const int b_r = (lane & 7) + ((lane >> 4) & 1) * 8;
    const int b_c = ((lane >> 3) & 1) * 8;

    const int nch = K >> 5;

    auto load_stage = [&](int st, int k0) {
        uint32_t base = sb + st*STAGE;
        #pragma unroll
        for (int c = tid; c < 512; c += 256) {
            int row = c >> 2, seg = c & 3;
            uint32_t d = base + row*80 + seg*16;
            CPA(d,         Ahi + (size_t)(bm + row)*K + k0 + seg*8);
            CPA(d + 10240, Alo + (size_t)(bm + row)*K + k0 + seg*8);
        }
        #pragma unroll
        for (int c = tid; c < BN2*4; c += 256) {
            int row = c >> 2, seg = c & 3;
            uint32_t d = base + 20480 + row*80 + seg*16;
            CPA(d,           Whi + (size_t)(bn + row)*K + k0 + seg*8);
            CPA(d + BN2*80,  Wlo + (size_t)(bn + row)*K + k0 + seg*8);
        }
        CPA_COMMIT();
    };

    load_stage(0, 0);

    for (int c = 0; c < nch; c++) {
        if (c + 1 < nch) { load_stage((c+1) & 1, (c+1) << 5); CPA_WAIT1(); }
        else             { CPA_WAIT0(); }
        __syncthreads();

        const uint32_t base = sb + (c & 1)*STAGE;
        #pragma unroll
        for (int ks = 0; ks < 2; ks++) {
            uint32_t ah[2][4], al[2][4];
            #pragma unroll
            for (int mi = 0; mi < 2; mi++) {
                uint32_t off = base + ((wm*32 + mi*16 + a_r)*PADH + ks*16 + a_c) * 2;
                ldsm4(ah[mi], off);
                ldsm4(al[mi], off + 10240);
            }
            uint32_t bh[NNI][2], bl[NNI][2];
            #pragma unroll
            for (int pi = 0; pi < NPI; pi++) {
                uint32_t off = base + 20480 + ((wn*WNT + pi*16 + b_r)*PADH + ks*16 + b_c) * 2;
                uint32_t t[4];
                ldsm4(t, off);
                bh[2*pi][0]=t[0]; bh[2*pi][1]=t[1]; bh[2*pi+1][0]=t[2]; bh[2*pi+1][1]=t[3];
                ldsm4(t, off + BN2*80);
                bl[2*pi][0]=t[0]; bl[2*pi][1]=t[1]; bl[2*pi+1][0]=t[2]; bl[2*pi+1][1]=t[3];
            }
            #pragma unroll
            for (int ni = 0; ni < NNI; ni++)
                #pragma unroll
                for (int mi = 0; mi < 2; mi++) {
                    mma16816(acc[mi][ni], ah[mi], bh[ni]);
                    mma16816(acc[mi][ni], ah[mi], bl[ni]);
                    mma16816(acc[mi][ni], al[mi], bh[ni]);
                }
        }
        __syncthreads();
    }

    const int gr = lane >> 2, gc = (lane & 3) * 2;
    #pragma unroll
    for (int mi = 0; mi < 2; mi++) {
        #pragma unroll
        for (int ni = 0; ni < NNI; ni++) {
            int r0 = bm + wm*32 + mi*16 + gr;
            int cc = bn + wn*WNT + ni*8 + gc;
            float2 v0 = make_float2(acc[mi][ni][0], acc[mi][ni][1]);
            float2 v1 = make_float2(acc[mi][ni][2], acc[mi][ni][3]);
            if (EPI != 3 && bias) {
                float2 bz = *reinterpret_cast<const float2*>(bias + cc);
                v0.x += bz.x; v0.y += bz.y; v1.x += bz.x; v1.y += bz.y;
            }
            if (EPI == 1) {
                float2 r0v = *reinterpret_cast<const float2*>(res + (size_t)r0*N + cc);
                float2 r1v = *reinterpret_cast<const float2*>(res + (size_t)(r0+8)*N + cc);
                v0.x += r0v.x; v0.y += r0v.y; v1.x += r1v.x; v1.y += r1v.y;
            }
            if (EPI == 2) {
                v0.x = 0.5f*v0.x*(1.0f + erff(v0.x*0.7071067811865475f));
                v0.y = 0.5f*v0.y*(1.0f + erff(v0.y*0.7071067811865475f));
                v1.x = 0.5f*v1.x*(1.0f + erff(v1.x*0.7071067811865475f));
                v1.y = 0.5f*v1.y*(1.0f + erff(v1.y*0.7071067811865475f));
            }
            if (EPI == 3) {
                if (cc < 256) {   // MQ region: fp32, row stride 256
                    *reinterpret_cast<float2*>(C + (size_t)r0*256 + cc)     = v0;
                    *reinterpret_cast<float2*>(C + (size_t)(r0+8)*256 + cc) = v1;
                } else {          // CD region: bf16 split, row stride 128
                    int c2 = cc - 256;
                    bf162 l0, l1;
                    bf162 h0 = split_hi(v0.x, v0.y, l0);
                    bf162 h1 = split_hi(v1.x, v1.y, l1);
                    *reinterpret_cast<bf162*>(Chi + (size_t)r0*128 + c2)     = h0;
                    *reinterpret_cast<bf162*>(Clo + (size_t)r0*128 + c2)     = l0;
                    *reinterpret_cast<bf162*>(Chi + (size_t)(r0+8)*128 + c2) = h1;
                    *reinterpret_cast<bf162*>(Clo + (size_t)(r0+8)*128 + c2) = l1;
                }
            } else if (OSPLIT) {
                bf162 l0, l1;
                bf162 h0 = split_hi(v0.x, v0.y, l0);
                bf162 h1 = split_hi(v1.x, v1.y, l1);
                *reinterpret_cast<bf162*>(Chi + (size_t)r0*N + cc)     = h0;
                *reinterpret_cast<bf162*>(Clo + (size_t)r0*N + cc)     = l0;
                *reinterpret_cast<bf162*>(Chi + (size_t)(r0+8)*N + cc) = h1;
                *reinterpret_cast<bf162*>(Clo + (size_t)(r0+8)*N + cc) = l1;
            } else {
                *reinterpret_cast<float2*>(C + (size_t)r0*N + cc)     = v0;
                *reinterpret_cast<float2*>(C + (size_t)(r0+8)*N + cc) = v1;
            }
        }
    }
}

// ---------------- feature attention over C=4 tokens (bf16 split output) ----------------
__global__ void feat_attn(const float* __restrict__ QKV,
                          bf16* __restrict__ AOh, bf16* __restrict__ AOl) {
    int s = blockIdx.x;
    int h = threadIdx.x >> 5;
    int lane = threadIdx.x & 31;
    float q[4], k[4], v[4];
    #pragma unroll
    for (int c = 0; c < 4; c++) {
        const float* row = QKV + (size_t)(s*4 + c) * 768;
        q[c] = row[h*32 + lane];
        k[c] = row[256 + h*32 + lane];
        v[c] = row[512 + h*32 + lane];
    }
    float sc[4][4];
    #pragma unroll
    for (int a = 0; a < 4; a++)
        #pragma unroll
        for (int b = 0; b < 4; b++) {
            float p = q[a] * k[b];
            #pragma unroll
            for (int o = 16; o > 0; o >>= 1) p += __shfl_xor_sync(0xffffffffu, p, o);
            sc[a][b] = p * 0.17677669529663687f;
        }
    #pragma unroll
    for (int a = 0; a < 4; a++) {
        float mx = fmaxf(fmaxf(sc[a][0], sc[a][1]), fmaxf(sc[a][2], sc[a][3]));
        float e0 = expf(sc[a][0]-mx), e1 = expf(sc[a][1]-mx);
        float e2 = expf(sc[a][2]-mx), e3 = expf(sc[a][3]-mx);
        float den = e0 + e1 + e2 + e3;
        float o = (e0*v[0] + e1*v[1] + e2*v[2] + e3*v[3]) / den;
        bf16 oh = __float2bfloat16(o);
        bf16 ol = __float2bfloat16(o - __bfloat162float(oh));
        size_t idx = (size_t)(s*4 + a)*256 + h*32 + lane;
        AOh[idx] = oh;
        AOl[idx] = ol;
    }
}

// ---------------- layernorm, warp-per-token, layout remap, optional split out ----------------
__global__ void ln_kernel(const float* __restrict__ X, const float* __restrict__ g,
                          const float* __restrict__ b, float* __restrict__ Y,
                          bf16* __restrict__ Yhi, bf16* __restrict__ Ylo, int mode) {
    int t = blockIdx.x * 8 + (threadIdx.x >> 5);
    int lane = threadIdx.x & 31;
    const float* xr = X + (size_t)t * 256 + lane * 8;
    float4 x0 = *reinterpret_cast<const float4*>(xr);
    float4 x1 = *reinterpret_cast<const float4*>(xr + 4);
    float s = x0.x + x0.y + x0.z + x0.w + x1.x + x1.y + x1.z + x1.w;
    #pragma unroll
    for (int o = 16; o > 0; o >>= 1) s += __shfl_xor_sync(0xffffffffu, s, o);
    float m = s * (1.0f / 256.0f);
    float d[8] = {x0.x-m, x0.y-m, x0.z-m, x0.w-m, x1.x-m, x1.y-m, x1.z-m, x1.w-m};
    float vs = 0.f;
    #pragma unroll
    for (int i = 0; i < 8; i++) vs += d[i]*d[i];
    #pragma unroll
    for (int o = 16; o > 0; o >>= 1) vs += __shfl_xor_sync(0xffffffffu, vs, o);
    float inv = rsqrtf(vs * (1.0f/256.0f) + 1e-5f);
    float y[8];
    const float* gp = g + lane*8;
    const float* bp = b + lane*8;
    #pragma unroll
    for (int i = 0; i < 8; i++) y[i] = d[i]*inv*gp[i] + bp[i];
    int ot;
    if (mode == 0) ot = t;
    else if (mode == 1) { int bb = t >> 12, r = (t >> 2) & 1023, c = t & 3; ot = ((bb<<2)|c)*1024 + r; }
    else { int bf = t >> 10, r = t & 1023; int bb = bf >> 2, c = bf & 3; ot = bb*4096 + r*4 + c; }
    float* yr = Y + (size_t)ot * 256 + lane * 8;
    *reinterpret_cast<float4*>(yr)     = make_float4(y[0], y[1], y[2], y[3]);
    *reinterpret_cast<float4*>(yr + 4) = make_float4(y[4], y[5], y[6], y[7]);
    if (Yhi) {
        size_t o2 = (size_t)ot * 256 + lane * 8;
        #pragma unroll
        for (int i = 0; i < 4; i++) {
            bf162 lo;
            bf162 hi = split_hi(y[2*i], y[2*i+1], lo);
            *reinterpret_cast<bf162*>(Yhi + o2 + 2*i) = hi;
            *reinterpret_cast<bf162*>(Ylo + o2 + 2*i) = lo;
        }
    }
}

// ---------------- indexer: scales / quantize / score+topk ----------------
__global__ void idx_scales(const float* __restrict__ IQK, float* __restrict__ SC) {
    int bf = blockIdx.x, h = blockIdx.y, kind = blockIdx.z;
    int r0 = (kind == 1) ? SPLIT : 0;
    int r1 = (kind == 1) ? 1024 : SPLIT;
    int cb = (kind == 2) ? 32 : 0;
    int n = (r1 - r0) * 8;
    float m = 0.0f;
    for (int i = threadIdx.x; i < n; i += 256) {
        int r = r0 + (i >> 3), d = i & 7;
        m = fmaxf(m, fabsf(IQK[(size_t)(bf*1024 + r)*64 + cb + h*8 + d]));
    }
    __shared__ float sm[8];
    #pragma unroll
    for (int o = 16; o > 0; o >>= 1) m = fmaxf(m, __shfl_xor_sync(0xffffffffu, m, o));
    if ((threadIdx.x & 31) == 0) sm[threadIdx.x >> 5] = m;
    __syncthreads();
    if (threadIdx.x == 0) {
        float mm = sm[0];
        for (int i = 1; i < 8; i++) mm = fmaxf(mm, sm[i]);
        SC[kind*32 + bf*4 + h] = (mm + 1e-6f) / 127.0f;
    }
}

__global__ void idx_quant(const float* __restrict__ IQK, const float* __restrict__ SC,
                          int* __restrict__ QI, int* __restrict__ KI) {
    int idx = blockIdx.x * 256 + threadIdx.x;
    if (idx >= NTOK*32) return;
    int t = idx >> 5, j = idx & 31, h = j >> 3;
    int bf = t >> 10, r = t & 1023;
    char* qb = (char*)QI;
    char* kb = (char*)KI;
    float qs = SC[(r < SPLIT ? 0 : 1)*32 + bf*4 + h];
    float qv = rintf(IQK[(size_t)t*64 + j] / qs);
    qv = fminf(fmaxf(qv, -127.0f), 127.0f);
    qb[idx] = (char)(int)qv;
    if (r < SPLIT) {
        float ks = SC[64 + bf*4 + h];
        float kv = rintf(IQK[(size_t)t*64 + 32 + j] / ks);
        kv = fminf(fmaxf(kv, -127.0f), 127.0f);
        kb[idx] = (char)(int)kv;
    } else {
        kb[idx] = 0;
    }
}

__global__ void idx_topk(const int* __restrict__ QI, const int* __restrict__ KI,
                         const float* __restrict__ SC, const float* __restrict__ ow,
                         int* __restrict__ IDX) {
    int t = blockIdx.x;
    int bf = t >> 10, r = t & 1023;
    __shared__ int sq[8];
    __shared__ float ssc[4], sow[4];
    __shared__ float swv[8];
    __shared__ int swi[8];
    __shared__ int winner;
    if (threadIdx.x < 8) sq[threadIdx.x] = QI[t*8 + threadIdx.x];
    if (threadIdx.x < 4) {
        int h = threadIdx.x;
        float qs = SC[(r < SPLIT ? 0 : 1)*32 + bf*4 + h];
        ssc[h] = qs * SC[64 + bf*4 + h];
        sow[h] = ow[h];
    }
    __syncthreads();
    float rv[3];
    #pragma unroll
    for (int i = 0; i < 3; i++) {
        int k = threadIdx.x + i*256;
        const int* kw = KI + (size_t)(bf*1024 + k)*8;
        float acc = 0.f;
        #pragma unroll
        for (int h = 0; h < 4; h++) {
            int d = __dp4a(sq[2*h], kw[2*h], __dp4a(sq[2*h+1], kw[2*h+1], 0));
            acc += fmaxf((float)d * ssc[h], 0.0f) * sow[h];
        }
        rv[i] = acc;
    }
    const int lane = threadIdx.x & 31;
    for (int sel = 0; sel < TOPK_; sel++) {
        float bv = rv[0]; int bi = threadIdx.x;
        if (rv[1] > bv) { bv = rv[1]; bi = threadIdx.x + 256; }
        if (rv[2] > bv) { bv = rv[2]; bi = threadIdx.x + 512; }
        #pragma unroll
        for (int o = 16; o > 0; o >>= 1) {
            float ov = __shfl_xor_sync(0xffffffffu, bv, o);
            int   oi = __shfl_xor_sync(0xffffffffu, bi, o);
            if (ov > bv || (ov == bv && oi < bi)) { bv = ov; bi = oi; }
        }
        if (lane == 0) { swv[threadIdx.x >> 5] = bv; swi[threadIdx.x >> 5] = bi; }
        __syncthreads();
        if (threadIdx.x == 0) {
            float fv = swv[0]; int fi = swi[0];
            #pragma unroll
            for (int i = 1; i < 8; i++)
                if (swv[i] > fv || (swv[i] == fv && swi[i] < fi)) { fv = swv[i]; fi = swi[i]; }
            IDX[t*TOPK_ + sel] = fi;
            winner = fi;
        }
        __syncthreads();
        int w = winner;
        if ((w & 255) == threadIdx.x) rv[w >> 8] = -FLT_MAX;
    }
}

// ---------------- sparse MLA attention over top-32 keys (bf16 split out) ----------------
__global__ void mla_attn(const float* __restrict__ MQ, const float* __restrict__ KV,
                         const int* __restrict__ IDX,
                         bf16* __restrict__ AO2h, bf16* __restrict__ AO2l) {
    int t = blockIdx.x;
    int bf = t >> 10;
    int h = threadIdx.x >> 5, lane = threadIdx.x & 31;
    __shared__ int sidx[32];
    if (threadIdx.x < 32) sidx[threadIdx.x] = IDX[t*TOPK_ + threadIdx.x];
    __syncthreads();
    float q = MQ[(size_t)t*256 + h*32 + lane];
    float myscore = 0.0f;
    for (int j = 0; j < 32; j++) {
        int kt = bf*1024 + sidx[j];
        float kk = KV[(size_t)kt*512 + h*32 + lane];
        float p = q * kk;
        #pragma unroll
        for (int o = 16; o > 0; o >>= 1) p += __shfl_xor_sync(0xffffffffu, p, o);
        if (lane == j) myscore = p * 0.17677669529663687f;
    }
    float mx = myscore;
    #pragma unroll
    for (int o = 16; o > 0; o >>= 1) mx = fmaxf(mx, __shfl_xor_sync(0xffffffffu, mx, o));
    float e = expf(myscore - mx);
    float s = e;
    #pragma unroll
    for (int o = 16; o > 0; o >>= 1) s += __shfl_xor_sync(0xffffffffu, s, o);
    float w = e / s;
    float acc = 0.0f;
    for (int j = 0; j < 32; j++) {
        float wj = __shfl_sync(0xffffffffu, w, j);
        int kt = bf*1024 + sidx[j];
        acc += wj * KV[(size_t)kt*512 + 256 + h*32 + lane];
    }
    bf16 oh = __float2bfloat16(acc);
    bf16 ol = __float2bfloat16(acc - __bfloat162float(oh));
    size_t idx = (size_t)t*256 + h*32 + lane;
    AO2h[idx] = oh;
    AO2l[idx] = ol;
}

// ---------------- host launcher ----------------
static float* symF(const void* sym) { void* p = nullptr; cudaGetSymbolAddress(&p, sym); return (float*)p; }
static int*   symI(const void* sym) { void* p = nullptr; cudaGetSymbolAddress(&p, sym); return (int*)p; }
static bf16*  symB(const void* sym) { void* p = nullptr; cudaGetSymbolAddress(&p, sym); return (bf16*)p; }

extern "C" void kernel_launch(void* const* d_in, const int* in_sizes, int n_in,
                              void* d_out, int out_size) {
    (void)in_sizes; (void)n_in; (void)out_size;
    const float* src      = (const float*)d_in[0];
    const float* fa_in_w  = (const float*)d_in[2];
    const float* fa_in_b  = (const float*)d_in[3];
    const float* fa_out_w = (const float*)d_in[4];
    const float* fa_out_b = (const float*)d_in[5];
    const float* n1g = (const float*)d_in[6];
    const float* n1b = (const float*)d_in[7];
    const float* iqw = (const float*)d_in[8];
    const float* ikw = (const float*)d_in[9];
    const float* iow = (const float*)d_in[10];
    const float* mqw = (const float*)d_in[11];
    const float* mdw = (const float*)d_in[12];
    const float* muw = (const float*)d_in[13];
    const float* mow = (const float*)d_in[14];
    const float* n2g = (const float*)d_in[15];
    const float* n2b = (const float*)d_in[16];
    const float* l1w = (const float*)d_in[17];
    const float* l1b = (const float*)d_in[18];
    const float* l2w = (const float*)d_in[19];
    const float* l2b = (const float*)d_in[20];
    const float* n3g = (const float*)d_in[21];
    const float* n3b = (const float*)d_in[22];

    float* QKV = symF(g_QKV); float* X   = symF(g_X);   float* ST  = symF(g_ST);
    float* IQK = symF(g_IQK); float* SC  = symF(g_SC);
    int*   QI  = symI(g_QI);  int*   KI  = symI(g_KI);  int*   IDX = symI(g_IDX);
    float* MQ  = symF(g_MQ);  float* KV  = symF(g_KV);  float* ST2 = symF(g_ST2);
    float* X2  = symF(g_X2);  float* X3  = symF(g_X3);
    bf16 *SRCh=symB(g_SRCh), *SRCl=symB(g_SRCl);
    bf16 *AOh=symB(g_AOh),   *AOl=symB(g_AOl);
    bf16 *STh=symB(g_STh),   *STl=symB(g_STl);
    bf16 *CDh=symB(g_CDh),   *CDl=symB(g_CDl);
    bf16 *AO2h=symB(g_AO2h), *AO2l=symB(g_AO2l);
    bf16 *X2h=symB(g_X2h),   *X2l=symB(g_X2l);
    bf16 *H1h=symB(g_H1h),   *H1l=symB(g_H1l);
    bf16 *Wh=symB(g_Whi),    *Wl=symB(g_Wlo);

    static cudaStream_t sW = nullptr, sB = nullptr;
    static cudaEvent_t evRoot = nullptr, evFA = nullptr, evW = nullptr, ev1 = nullptr, evB = nullptr;
    if (!sW) {
        cudaStreamCreateWithFlags(&sW, cudaStreamNonBlocking);
        cudaStreamCreateWithFlags(&sB, cudaStreamNonBlocking);
        cudaEventCreateWithFlags(&evRoot, cudaEventDisableTiming);
        cudaEventCreateWithFlags(&evFA,  cudaEventDisableTiming);
        cudaEventCreateWithFlags(&evW,   cudaEventDisableTiming);
        cudaEventCreateWithFlags(&ev1,   cudaEventDisableTiming);
        cudaEventCreateWithFlags(&evB,   cudaEventDisableTiming);
        cudaFuncSetAttribute(hgemm<0,128,0>, cudaFuncAttributeMaxDynamicSharedMemorySize, 81920);
        cudaFuncSetAttribute(hgemm<2,128,1>, cudaFuncAttributeMaxDynamicSharedMemorySize, 81920);
        cudaFuncSetAttribute(hgemm<0,64,0>,  cudaFuncAttributeMaxDynamicSharedMemorySize, 61440);
        cudaFuncSetAttribute(hgemm<1,64,0>,  cudaFuncAttributeMaxDynamicSharedMemorySize, 61440);
        cudaFuncSetAttribute(hgemm<3,64,0>,  cudaFuncAttributeMaxDynamicSharedMemorySize, 61440);
    }

    dim3 blk(256);

    // Fork: weight conversions on side stream, overlapping src conversion / Stage A
    cudaEventRecord(evRoot, 0);
    cudaStreamWaitEvent(sW, evRoot, 0);
    wcvt_fa<<<256, blk, 0, sW>>>(fa_in_w, fa_out_w, Wh, Wl);
    cudaEventRecord(evFA, sW);
    wcvt6<<<752, blk, 0, sW>>>(mqw, mdw, muw, mow, l1w, l2w, iqw, ikw, Wh, Wl);
    cudaEventRecord(evW, sW);

    // Stage A (main stream)
    cvt_split<<<2048, blk>>>(src, SRCh, SRCl, NTOK*256);
    cudaStreamWaitEvent(0, evFA, 0);
    hgemm<0,128,0><<<dim3(6,64), blk, 81920>>>(SRCh, SRCl, Wh+W_FAIN, Wl+W_FAIN,
        fa_in_b, nullptr, QKV, nullptr, nullptr, NTOK, 768, 256);
    feat_attn<<<2048, blk>>>(QKV, AOh, AOl);
    hgemm<1,64,0><<<dim3(4,64), blk, 61440>>>(AOh, AOl, Wh+W_FAOUT, Wl+W_FAOUT,
        fa_out_b, src, X, nullptr, nullptr, NTOK, 256, 256);
    ln_kernel<<<NTOK/8, blk>>>(X, n1g, n1b, ST, STh, STl, 1);

    // Fork indexer branch
    cudaEventRecord(ev1, 0);
    cudaStreamWaitEvent(sB, ev1, 0);
    cudaStreamWaitEvent(sB, evW, 0);
    hgemm<0,64,0><<<dim3(1,64), blk, 61440, sB>>>(STh, STl, Wh+W_IDX, Wl+W_IDX,
        nullptr, nullptr, IQK, nullptr, nullptr, NTOK, 64, 256);
    idx_scales<<<dim3(8,4,3), blk, 0, sB>>>(IQK, SC);
    idx_quant<<<NTOK*32/256, blk, 0, sB>>>(IQK, SC, QI, KI);
    idx_topk<<<NTOK, blk, 0, sB>>>(QI, KI, SC, iow, IDX);
    cudaEventRecord(evB, sB);

    // Stage C GEMMs (main, concurrent with indexer branch)
    cudaStreamWaitEvent(0, evW, 0);
    // merged MQ (cols 0..255, fp32) + MD (cols 256..383, split) GEMM, N=384
    hgemm<3,64,0><<<dim3(6,64), blk, 61440>>>(STh, STl, Wh+W_MQ, Wl+W_MQ,
        nullptr, nullptr, MQ, CDh, CDl, NTOK, 384, 256);
    hgemm<0,128,0><<<dim3(4,64), blk, 81920>>>(CDh, CDl, Wh+W_MU, Wl+W_MU,
        nullptr, nullptr, KV, nullptr, nullptr, NTOK, 512, 128);

    // Join + attention
    cudaStreamWaitEvent(0, evB, 0);
    mla_attn<<<NTOK, blk>>>(MQ, KV, IDX, AO2h, AO2l);
    hgemm<1,64,0><<<dim3(4,64), blk, 61440>>>(AO2h, AO2l, Wh+W_MO, Wl+W_MO,
        nullptr, ST, ST2, nullptr, nullptr, NTOK, 256, 256);

    // Stage D
    ln_kernel<<<NTOK/8, blk>>>(ST2, n2g, n2b, X2, X2h, X2l, 2);
    hgemm<2,128,1><<<dim3(8,64), blk, 81920>>>(X2h, X2l, Wh+W_L1, Wl+W_L1,
        l1b, nullptr, nullptr, H1h, H1l, NTOK, 1024, 256);
    hgemm<1,64,0><<<dim3(4,64), blk, 61440>>>(H1h, H1l, Wh+W_L2, Wl+W_L2,
        l2b, X2, X3, nullptr, nullptr, NTOK, 256, 1024);
    ln_kernel<<<NTOK/8, blk>>>(X3, n3g, n3b, (float*)d_out, nullptr, nullptr, 0);
}